// round 15
// baseline (speedup 1.0000x reference)
#include <cuda_runtime.h>
#include <cuda_bf16.h>
#include <cuda_fp16.h>
#include <math.h>
#include <cstdint>

#define TOKENS 4096   // B*T
#define DMODEL 2048   // NH*HD
#define TSEQ   2048
#define NHEADS 16
#define HDIM   128
#define QLATD  1024
#define KVLATD 512

typedef __nv_bfloat16 bf16;

// ---------------- scratch (device globals; no allocation allowed) ----------
__device__ float g_q  [TOKENS * DMODEL];
__device__ float g_k  [TOKENS * DMODEL];
__device__ bf16 g_xh [TOKENS * DMODEL],  g_xl [TOKENS * DMODEL];
__device__ bf16 g_qlh[TOKENS * QLATD],   g_qll[TOKENS * QLATD];
__device__ bf16 g_kvh[TOKENS * KVLATD],  g_kvl[TOKENS * KVLATD];
__device__ bf16 g_qh [TOKENS * DMODEL],  g_ql [TOKENS * DMODEL];
__device__ bf16 g_kh [TOKENS * DMODEL],  g_kl [TOKENS * DMODEL];
__device__ half g_vf [TOKENS * DMODEL];            // V single fp16
__device__ half g_aof[TOKENS * DMODEL];            // attention out, single fp16
__device__ half g_owf[DMODEL * DMODEL];            // o_w single fp16
__device__ bf16 g_wqah[QLATD * DMODEL],  g_wqal[QLATD * DMODEL];
__device__ bf16 g_wqbh[DMODEL * QLATD],  g_wqbl[DMODEL * QLATD];
__device__ bf16 g_wkvh[KVLATD * DMODEL], g_wkvl[KVLATD * DMODEL];
__device__ bf16 g_wkbh[DMODEL * KVLATD], g_wkbl[DMODEL * KVLATD];
__device__ bf16 g_wvbh[DMODEL * KVLATD], g_wvbl[DMODEL * KVLATD];

// ================= helpers (baseline PTX, no "a"-features) =================
__device__ __forceinline__ uint32_t smem_u32(const void* p) {
    uint32_t a;
    asm("{ .reg .u64 t; cvta.to.shared.u64 t, %1; cvt.u32.u64 %0, t; }"
        : "=r"(a) : "l"(p));
    return a;
}
__device__ __forceinline__ float ex2(float x) {
    float y;
    asm("ex2.approx.ftz.f32 %0, %1;" : "=f"(y) : "f"(x));
    return y;
}

#define CP_ASYNC16(sa, gp) \
    asm volatile("cp.async.cg.shared.global [%0], [%1], 16;" :: "r"(sa), "l"(gp))
#define CP_COMMIT() asm volatile("cp.async.commit_group;" ::: "memory")
#define CP_WAIT0()  asm volatile("cp.async.wait_group 0;" ::: "memory")
#define CP_WAIT1()  asm volatile("cp.async.wait_group 1;" ::: "memory")

#define LDM4(r, addr) \
    asm volatile("ldmatrix.sync.aligned.m8n8.x4.shared.b16 {%0,%1,%2,%3}, [%4];" \
                 : "=r"((r)[0]), "=r"((r)[1]), "=r"((r)[2]), "=r"((r)[3]) : "r"(addr))
#define LDM4T(r, addr) \
    asm volatile("ldmatrix.sync.aligned.m8n8.x4.trans.shared.b16 {%0,%1,%2,%3}, [%4];" \
                 : "=r"((r)[0]), "=r"((r)[1]), "=r"((r)[2]), "=r"((r)[3]) : "r"(addr))
#define MMA_BF16(d, a, b) \
    asm volatile("mma.sync.aligned.m16n8k16.row.col.f32.bf16.bf16.f32 " \
                 "{%0,%1,%2,%3}, {%4,%5,%6,%7}, {%8,%9}, {%0,%1,%2,%3};" \
                 : "+f"((d)[0]), "+f"((d)[1]), "+f"((d)[2]), "+f"((d)[3]) \
                 : "r"((a)[0]), "r"((a)[1]), "r"((a)[2]), "r"((a)[3]), \
                   "r"((b)[0]), "r"((b)[1]))
#define MMA_F16(d, a, b) \
    asm volatile("mma.sync.aligned.m16n8k16.row.col.f32.f16.f16.f32 " \
                 "{%0,%1,%2,%3}, {%4,%5,%6,%7}, {%8,%9}, {%0,%1,%2,%3};" \
                 : "+f"((d)[0]), "+f"((d)[1]), "+f"((d)[2]), "+f"((d)[3]) \
                 : "r"((a)[0]), "r"((a)[1]), "r"((a)[2]), "r"((a)[3]), \
                   "r"((b)[0]), "r"((b)[1]))

__device__ __forceinline__ void split2(float v, bf16& h, bf16& l) {
    h = __float2bfloat16_rn(v);
    l = __float2bfloat16_rn(v - __bfloat162float(h));
}
__device__ __forceinline__ void pack_hilo(float a, float b, uint32_t& h, uint32_t& l) {
    bf16 ha, la, hb, lb;
    split2(a, ha, la);
    split2(b, hb, lb);
    __nv_bfloat162 th(ha, hb), tl(la, lb);
    h = *(uint32_t*)&th;
    l = *(uint32_t*)&tl;
}
__device__ __forceinline__ uint32_t pack_h2(float a, float b) {
    __half2 t = __floats2half2_rn(a, b);
    return *(uint32_t*)&t;
}

// ============= 3-term bf16 GEMM: C = (Ah+Al)(Bh+Bl)^T ======================
// 128x128 tile, BK=32, cp.async 2-stage, 4 warps each 64x64 (R10 config).
#define SSTR 40
#define G_ARR  10240
#define G_STG  (4 * G_ARR)
#define GEMM_SMEM_BYTES (2 * G_STG)

__global__ __launch_bounds__(128)
void gemm_mma(const bf16* __restrict__ Ah, const bf16* __restrict__ Al,
              const bf16* __restrict__ Bh, const bf16* __restrict__ Bl,
              float* __restrict__ Cf, bf16* __restrict__ Ch,
              bf16* __restrict__ Cl, half* __restrict__ Cf16,
              int M, int N, int K) {
    extern __shared__ bf16 sg[];
    const uint32_t sb = smem_u32(sg);

    const int tid = threadIdx.x, lane = tid & 31, warp = tid >> 5;
    const int wm = (warp & 1) * 64, wn = (warp >> 1) * 64;
    const int bm = blockIdx.y * 128, bn = blockIdx.x * 128;

    const int lrA = lane & 15, lcA = (lane >> 4) << 3;
    const int l7 = lane & 7;
    const int k8 = ((lane >> 3) & 1) << 3;
    const int n8 = ((lane >> 4) & 1) << 3;

    float c[4][8][4];
#pragma unroll
    for (int i = 0; i < 4; i++)
#pragma unroll
        for (int j = 0; j < 8; j++)
#pragma unroll
            for (int k = 0; k < 4; k++) c[i][j][k] = 0.f;

    auto load_stage = [&](int kt, int s) {
        uint32_t so = sb + (uint32_t)s * G_STG;
#pragma unroll
        for (int i = 0; i < 4; i++) {
            int idx = tid + i * 128;
            int row = idx >> 2, cc = idx & 3;
            size_t gA = (size_t)(bm + row) * K + kt + cc * 8;
            size_t gB = (size_t)(bn + row) * K + kt + cc * 8;
            uint32_t off = (uint32_t)(row * (SSTR * 2) + cc * 16);
            CP_ASYNC16(so + off,             Ah + gA);
            CP_ASYNC16(so + G_ARR + off,     Al + gA);
            CP_ASYNC16(so + 2 * G_ARR + off, Bh + gB);
            CP_ASYNC16(so + 3 * G_ARR + off, Bl + gB);
        }
    };

    const int nkt = K >> 5;
    load_stage(0, 0);
    CP_COMMIT();

    for (int kt = 0; kt < nkt; kt++) {
        if (kt + 1 < nkt) {
            load_stage((kt + 1) << 5, (kt + 1) & 1);
            CP_COMMIT();
            CP_WAIT1();
        } else {
            CP_WAIT0();
        }
        __syncthreads();

        const uint32_t aAh = sb + (uint32_t)(kt & 1) * G_STG;
        const uint32_t aAl = aAh + G_ARR;
        const uint32_t aBh = aAh + 2 * G_ARR;
        const uint32_t aBl = aAh + 3 * G_ARR;

#pragma unroll
        for (int ks = 0; ks < 32; ks += 16) {
            uint32_t bh[8][2], bl[8][2], t[4];
#pragma unroll
            for (int p = 0; p < 4; p++) {
                uint32_t off = (uint32_t)(((wn + p * 16 + n8 + l7) * SSTR + ks + k8) * 2);
                LDM4(t, aBh + off);
                bh[2 * p][0] = t[0]; bh[2 * p][1] = t[1];
                bh[2 * p + 1][0] = t[2]; bh[2 * p + 1][1] = t[3];
                LDM4(t, aBl + off);
                bl[2 * p][0] = t[0]; bl[2 * p][1] = t[1];
                bl[2 * p + 1][0] = t[2]; bl[2 * p + 1][1] = t[3];
            }
#pragma unroll
            for (int mt = 0; mt < 4; mt++) {
                uint32_t off = (uint32_t)(((wm + mt * 16 + lrA) * SSTR + ks + lcA) * 2);
                uint32_t ah[4], al[4];
                LDM4(ah, aAh + off);
                LDM4(al, aAl + off);
#pragma unroll
                for (int nt = 0; nt < 8; nt++) {
                    MMA_BF16(c[mt][nt], ah, bh[nt]);
                    MMA_BF16(c[mt][nt], ah, bl[nt]);
                    MMA_BF16(c[mt][nt], al, bh[nt]);
                }
            }
        }
        __syncthreads();
    }

    const int er = lane >> 2, ec = (lane & 3) << 1;
#pragma unroll
    for (int mt = 0; mt < 4; mt++) {
#pragma unroll
        for (int nt = 0; nt < 8; nt++) {
            size_t r0 = (size_t)(bm + wm + mt * 16 + er);
            int c0 = bn + wn + nt * 8 + ec;
            float v0 = c[mt][nt][0], v1 = c[mt][nt][1];
            float v2 = c[mt][nt][2], v3 = c[mt][nt][3];
            if (Cf) {
                *(float2*)(Cf + r0 * N + c0)       = make_float2(v0, v1);
                *(float2*)(Cf + (r0 + 8) * N + c0) = make_float2(v2, v3);
            }
            if (Ch) {
                uint32_t h01, l01, h23, l23;
                pack_hilo(v0, v1, h01, l01);
                pack_hilo(v2, v3, h23, l23);
                *(uint32_t*)(Ch + r0 * N + c0)       = h01;
                *(uint32_t*)(Ch + (r0 + 8) * N + c0) = h23;
                *(uint32_t*)(Cl + r0 * N + c0)       = l01;
                *(uint32_t*)(Cl + (r0 + 8) * N + c0) = l23;
            }
            if (Cf16) {
                *(uint32_t*)(Cf16 + r0 * N + c0)       = pack_h2(v0, v1);
                *(uint32_t*)(Cf16 + (r0 + 8) * N + c0) = pack_h2(v2, v3);
            }
        }
    }
}

// ============= single-product fp16 GEMM (for output projection) ============
#define H_ARR 10240
#define H_STG (2 * H_ARR)
#define GEMMH_SMEM_BYTES (2 * H_STG)   // 40960

__global__ __launch_bounds__(128)
void gemm_f16(const half* __restrict__ A, const half* __restrict__ B,
              float* __restrict__ Cf, int M, int N, int K) {
    extern __shared__ half sh[];
    const uint32_t sb = smem_u32(sh);

    const int tid = threadIdx.x, lane = tid & 31, warp = tid >> 5;
    const int wm = (warp & 1) * 64, wn = (warp >> 1) * 64;
    const int bm = blockIdx.y * 128, bn = blockIdx.x * 128;

    const int lrA = lane & 15, lcA = (lane >> 4) << 3;
    const int l7 = lane & 7;
    const int k8 = ((lane >> 3) & 1) << 3;
    const int n8 = ((lane >> 4) & 1) << 3;

    float c[4][8][4];
#pragma unroll
    for (int i = 0; i < 4; i++)
#pragma unroll
        for (int j = 0; j < 8; j++)
#pragma unroll
            for (int k = 0; k < 4; k++) c[i][j][k] = 0.f;

    auto load_stage = [&](int kt, int s) {
        uint32_t so = sb + (uint32_t)s * H_STG;
#pragma unroll
        for (int i = 0; i < 4; i++) {
            int idx = tid + i * 128;
            int row = idx >> 2, cc = idx & 3;
            size_t gA = (size_t)(bm + row) * K + kt + cc * 8;
            size_t gB = (size_t)(bn + row) * K + kt + cc * 8;
            uint32_t off = (uint32_t)(row * (SSTR * 2) + cc * 16);
            CP_ASYNC16(so + off,         A + gA);
            CP_ASYNC16(so + H_ARR + off, B + gB);
        }
    };

    const int nkt = K >> 5;
    load_stage(0, 0);
    CP_COMMIT();

    for (int kt = 0; kt < nkt; kt++) {
        if (kt + 1 < nkt) {
            load_stage((kt + 1) << 5, (kt + 1) & 1);
            CP_COMMIT();
            CP_WAIT1();
        } else {
            CP_WAIT0();
        }
        __syncthreads();

        const uint32_t aA = sb + (uint32_t)(kt & 1) * H_STG;
        const uint32_t aB = aA + H_ARR;

#pragma unroll
        for (int ks = 0; ks < 32; ks += 16) {
            uint32_t bh[8][2], t[4];
#pragma unroll
            for (int p = 0; p < 4; p++) {
                uint32_t off = (uint32_t)(((wn + p * 16 + n8 + l7) * SSTR + ks + k8) * 2);
                LDM4(t, aB + off);
                bh[2 * p][0] = t[0]; bh[2 * p][1] = t[1];
                bh[2 * p + 1][0] = t[2]; bh[2 * p + 1][1] = t[3];
            }
#pragma unroll
            for (int mt = 0; mt < 4; mt++) {
                uint32_t off = (uint32_t)(((wm + mt * 16 + lrA) * SSTR + ks + lcA) * 2);
                uint32_t ah[4];
                LDM4(ah, aA + off);
#pragma unroll
                for (int nt = 0; nt < 8; nt++)
                    MMA_F16(c[mt][nt], ah, bh[nt]);
            }
        }
        __syncthreads();
    }

    const int er = lane >> 2, ec = (lane & 3) << 1;
#pragma unroll
    for (int mt = 0; mt < 4; mt++) {
#pragma unroll
        for (int nt = 0; nt < 8; nt++) {
            size_t r0 = (size_t)(bm + wm + mt * 16 + er);
            int c0 = bn + wn + nt * 8 + ec;
            *(float2*)(Cf + r0 * N + c0)       = make_float2(c[mt][nt][0], c[mt][nt][1]);
            *(float2*)(Cf + (r0 + 8) * N + c0) = make_float2(c[mt][nt][2], c[mt][nt][3]);
        }
    }
}

// ---------------- fp32 -> (bf16 hi, bf16 lo) ------------------------------
__global__ __launch_bounds__(256)
void conv_hilo(const float* __restrict__ in, bf16* __restrict__ hi,
               bf16* __restrict__ lo, int n4) {
    int i = blockIdx.x * 256 + threadIdx.x;
    if (i >= n4) return;
    float4 x = ((const float4*)in)[i];
    float v[4] = {x.x, x.y, x.z, x.w};
    bf16 h[4], l[4];
#pragma unroll
    for (int j = 0; j < 4; j++) split2(v[j], h[j], l[j]);
    ((__nv_bfloat162*)hi)[i * 2]     = __nv_bfloat162(h[0], h[1]);
    ((__nv_bfloat162*)hi)[i * 2 + 1] = __nv_bfloat162(h[2], h[3]);
    ((__nv_bfloat162*)lo)[i * 2]     = __nv_bfloat162(l[0], l[1]);
    ((__nv_bfloat162*)lo)[i * 2 + 1] = __nv_bfloat162(l[2], l[3]);
}

// ---------------- fp32 -> fp16 (single) ------------------------------------
__global__ __launch_bounds__(256)
void conv_f16(const float* __restrict__ in, half* __restrict__ out, int n4) {
    int i = blockIdx.x * 256 + threadIdx.x;
    if (i >= n4) return;
    float4 x = ((const float4*)in)[i];
    ((uint32_t*)out)[i * 2]     = pack_h2(x.x, x.y);
    ((uint32_t*)out)[i * 2 + 1] = pack_h2(x.z, x.w);
}

// -------- fused per-head RMSNorm + RoPE, emitting bf16 hi/lo ---------------
__global__ __launch_bounds__(128)
void norm_rope_kernel(const float* __restrict__ X, const float* __restrict__ w,
                      bf16* __restrict__ H, bf16* __restrict__ L) {
    const int blk = blockIdx.x;
    const int token = blk >> 4, h = blk & 15;
    const int t = token & (TSEQ - 1);
    const int i = threadIdx.x;
    const size_t off = (size_t)token * DMODEL + h * HDIM + i;
    float x = X[off];
    float ss = x * x;
#pragma unroll
    for (int o = 16; o; o >>= 1)
        ss += __shfl_xor_sync(0xffffffffu, ss, o);
    __shared__ float sred[4];
    if ((i & 31) == 0) sred[i >> 5] = ss;
    __syncthreads();
    ss = sred[0] + sred[1] + sred[2] + sred[3];
    float rn = rsqrtf(ss * (1.0f / HDIM) + 1e-6f);
    float xn = x * rn * w[i];
    __shared__ float sh[HDIM];
    sh[i] = xn;
    __syncthreads();
    const int f = i & 63;
    float invf = exp2f((float)f * (-13.287712379549449f / 64.0f));
    float ang = (float)t * invf;
    float c, s;
    sincosf(ang, &s, &c);
    float partner = (i < 64) ? -sh[i + 64] : sh[i - 64];
    float out = xn * c + partner * s;
    bf16 hh, ll;
    split2(out, hh, ll);
    H[off] = hh;
    L[off] = ll;
}

// ======== causal flash attention v3: bf16-split S, single-fp16 PV ==========
#define QK_STR 136
#define FQ_H 0
#define FQ_L 34816
#define FKV0 69632
#define FKVS 52224
#define SK_H 0
#define SK_L 17408
#define SV_F 34816
#define FLASH_SMEM_BYTES (69632 + 2 * 52224)   // 174080
#define SCL 0.1275175f     // (1/sqrt(128)) * log2(e)

__global__ __launch_bounds__(256, 1)
void flash_mma(const bf16* __restrict__ Qh, const bf16* __restrict__ Ql,
               const bf16* __restrict__ Kh, const bf16* __restrict__ Kl,
               const half* __restrict__ Vf, half* __restrict__ Of) {
    extern __shared__ char smraw[];
    const uint32_t sb = smem_u32(smraw);

    const int qb = (TSEQ / 128 - 1) - blockIdx.x;   // heavy CTAs first
    const int pair = blockIdx.y;
    const int b = pair >> 4, h = pair & 15;
    const int tid = threadIdx.x, lane = tid & 31, warp = tid >> 5;
    const int wm = warp * 16;
    const int er = lane >> 2, ec = (lane & 3) << 1;
    const int lrA = lane & 15, lcA = (lane >> 4) << 3;
    const int l7 = lane & 7;
    const int k8 = ((lane >> 3) & 1) << 3;
    const int n8 = ((lane >> 4) & 1) << 3;

    const size_t bT = (size_t)b * TSEQ;
    const int hoff = h * HDIM;

#pragma unroll
    for (int i = 0; i < 8; i++) {
        int idx = tid + i * 256;
        int row = idx >> 4, ch = idx & 15;
        size_t g = (bT + qb * 128 + row) * DMODEL + hoff + ch * 8;
        uint32_t off = (uint32_t)(row * (QK_STR * 2) + ch * 16);
        CP_ASYNC16(sb + FQ_H + off, Qh + g);
        CP_ASYNC16(sb + FQ_L + off, Ql + g);
    }
    auto load_kv = [&](int kb, int s) {
        uint32_t so = sb + FKV0 + (uint32_t)s * FKVS;
#pragma unroll
        for (int i = 0; i < 4; i++) {
            int idx = tid + i * 256;
            int row = idx >> 4, ch = idx & 15;
            size_t g = (bT + kb * 64 + row) * DMODEL + hoff + ch * 8;
            uint32_t off = (uint32_t)(row * (QK_STR * 2) + ch * 16);
            CP_ASYNC16(so + SK_H + off, Kh + g);
            CP_ASYNC16(so + SK_L + off, Kl + g);
            CP_ASYNC16(so + SV_F + off, Vf + g);
        }
    };
    load_kv(0, 0);
    CP_COMMIT();

    float o[16][4];
#pragma unroll
    for (int i = 0; i < 16; i++)
#pragma unroll
        for (int j = 0; j < 4; j++) o[i][j] = 0.f;
    float m0 = -1e30f, m1 = -1e30f, l0 = 0.f, l1 = 0.f;

    const int grow_lo = qb * 128 + wm + er;
    const int grow_hi = grow_lo + 8;
    const int row_max = qb * 128 + wm + 15;
    const int nkb = 2 * qb + 2;

    for (int kb = 0; kb < nkb; kb++) {
        if (kb + 1 < nkb) {
            load_kv(kb + 1, (kb + 1) & 1);
            CP_COMMIT();
            CP_WAIT1();
        } else {
            CP_WAIT0();
        }
        __syncthreads();

        if (kb * 64 <= row_max) {   // causal per-warp skip
            const uint32_t sKV = sb + FKV0 + (uint32_t)(kb & 1) * FKVS;
            const uint32_t sKh = sKV + SK_H, sKl = sKV + SK_L;
            const uint32_t sV  = sKV + SV_F;

            float c[8][4];
#pragma unroll
            for (int i = 0; i < 8; i++)
#pragma unroll
                for (int j = 0; j < 4; j++) c[i][j] = 0.f;

#pragma unroll
            for (int ks = 0; ks < 8; ks++) {
                uint32_t ah[4], al[4];
                uint32_t offA = (uint32_t)(((wm + lrA) * QK_STR + ks * 16 + lcA) * 2);
                LDM4(ah, sb + FQ_H + offA);
                LDM4(al, sb + FQ_L + offA);
                uint32_t bh[8][2], bl[8][2], t[4];
#pragma unroll
                for (int p = 0; p < 4; p++) {
                    uint32_t offB = (uint32_t)(((p * 16 + n8 + l7) * QK_STR + ks * 16 + k8) * 2);
                    LDM4(t, sKh + offB);
                    bh[2 * p][0] = t[0]; bh[2 * p][1] = t[1];
                    bh[2 * p + 1][0] = t[2]; bh[2 * p + 1][1] = t[3];
                    LDM4(t, sKl + offB);
                    bl[2 * p][0] = t[0]; bl[2 * p][1] = t[1];
                    bl[2 * p + 1][0] = t[2]; bl[2 * p + 1][1] = t[3];
                }
#pragma unroll
                for (int nt = 0; nt < 8; nt++) {
                    MMA_BF16(c[nt], ah, bh[nt]);
                    MMA_BF16(c[nt], ah, bl[nt]);
                    MMA_BF16(c[nt], al, bh[nt]);
                }
            }

            float mx0 = -1e30f, mx1 = -1e30f;
#pragma unroll
            for (int nt = 0; nt < 8; nt++) {
                int col = kb * 64 + nt * 8 + ec;
#pragma unroll
                for (int j = 0; j < 2; j++) {
                    float s0 = c[nt][j] * SCL;
                    float s1 = c[nt][j + 2] * SCL;
                    if (col + j > grow_lo) s0 = -1e30f;
                    if (col + j > grow_hi) s1 = -1e30f;
                    c[nt][j] = s0; c[nt][j + 2] = s1;
                    mx0 = fmaxf(mx0, s0); mx1 = fmaxf(mx1, s1);
                }
            }
            mx0 = fmaxf(mx0, __shfl_xor_sync(0xffffffffu, mx0, 1));
            mx0 = fmaxf(mx0, __shfl_xor_sync(0xffffffffu, mx0, 2));
            mx1 = fmaxf(mx1, __shfl_xor_sync(0xffffffffu, mx1, 1));
            mx1 = fmaxf(mx1, __shfl_xor_sync(0xffffffffu, mx1, 2));
            float m0n = fmaxf(m0, mx0), m1n = fmaxf(m1, mx1);
            float a0 = ex2(m0 - m0n), a1 = ex2(m1 - m1n);
            m0 = m0n; m1 = m1n;

            float sum0 = 0.f, sum1 = 0.f;
#pragma unroll
            for (int nt = 0; nt < 8; nt++) {
                float p0 = ex2(c[nt][0] - m0n), p1 = ex2(c[nt][1] - m0n);
                float p2 = ex2(c[nt][2] - m1n), p3 = ex2(c[nt][3] - m1n);
                c[nt][0] = p0; c[nt][1] = p1; c[nt][2] = p2; c[nt][3] = p3;
                sum0 += p0 + p1; sum1 += p2 + p3;
            }
            sum0 += __shfl_xor_sync(0xffffffffu, sum0, 1);
            sum0 += __shfl_xor_sync(0xffffffffu, sum0, 2);
            sum1 += __shfl_xor_sync(0xffffffffu, sum1, 1);
            sum1 += __shfl_xor_sync(0xffffffffu, sum1, 2);
            l0 = l0 * a0 + sum0;
            l1 = l1 * a1 + sum1;
            if (a0 != 1.f || a1 != 1.f) {       // skip rescale when max unchanged
#pragma unroll
                for (int nt = 0; nt < 16; nt++) {
                    o[nt][0] *= a0; o[nt][1] *= a0;
                    o[nt][2] *= a1; o[nt][3] *= a1;
                }
            }

            // ---- O += P V : P single fp16 in registers, V single fp16 ----
#pragma unroll
            for (int kk = 0; kk < 4; kk++) {
                uint32_t ph[4];
                ph[0] = pack_h2(c[2 * kk][0],     c[2 * kk][1]);
                ph[1] = pack_h2(c[2 * kk][2],     c[2 * kk][3]);
                ph[2] = pack_h2(c[2 * kk + 1][0], c[2 * kk + 1][1]);
                ph[3] = pack_h2(c[2 * kk + 1][2], c[2 * kk + 1][3]);
#pragma unroll
                for (int p = 0; p < 8; p++) {
                    uint32_t vh[4];
                    uint32_t offV = (uint32_t)(((kk * 16 + l7 + k8) * QK_STR + p * 16 + n8) * 2);
                    LDM4T(vh, sV + offV);
                    uint32_t vh0[2] = {vh[0], vh[1]}, vh1[2] = {vh[2], vh[3]};
                    MMA_F16(o[2 * p], ph, vh0);
                    MMA_F16(o[2 * p + 1], ph, vh1);
                }
            }
        }
        __syncthreads();
    }

    float inv0 = 1.f / l0, inv1 = 1.f / l1;
    size_t tok_lo = (bT + (size_t)grow_lo) * DMODEL + hoff;
    size_t tok_hi = (bT + (size_t)grow_hi) * DMODEL + hoff;
#pragma unroll
    for (int nt = 0; nt < 16; nt++) {
        int col = nt * 8 + ec;
        *(uint32_t*)(Of + tok_lo + col) = pack_h2(o[nt][0] * inv0, o[nt][1] * inv0);
        *(uint32_t*)(Of + tok_hi + col) = pack_h2(o[nt][2] * inv1, o[nt][3] * inv1);
    }
}

// ---------------- launch (multi-stream fork/join, capture-safe) -------------
static inline void conv_on(cudaStream_t st, const float* in, bf16* h, bf16* l, int n) {
    int n4 = n / 4;
    conv_hilo<<<(n4 + 255) / 256, 256, 0, st>>>(in, h, l, n4);
}

extern "C" void kernel_launch(void* const* d_in, const int* in_sizes, int n_in,
                              void* d_out, int out_size) {
    const float* x      = (const float*)d_in[0];
    const float* q_a_w  = (const float*)d_in[2];
    const float* q_b_w  = (const float*)d_in[3];
    const float* kv_a_w = (const float*)d_in[4];
    const float* k_b_w  = (const float*)d_in[5];
    const float* v_b_w  = (const float*)d_in[6];
    const float* o_w    = (const float*)d_in[7];
    const float* q_nw   = (const float*)d_in[8];
    const float* k_nw   = (const float*)d_in[9];

    float *q, *k;
    bf16 *xh, *xl, *qlh, *qll, *kvh, *kvl, *qh, *ql, *kh, *kl;
    half *vf, *aof, *owf;
    bf16 *wqah, *wqal, *wqbh, *wqbl, *wkvh, *wkvl, *wkbh, *wkbl, *wvbh, *wvbl;
    cudaGetSymbolAddress((void**)&q, g_q);     cudaGetSymbolAddress((void**)&k, g_k);
    cudaGetSymbolAddress((void**)&xh, g_xh);   cudaGetSymbolAddress((void**)&xl, g_xl);
    cudaGetSymbolAddress((void**)&qlh, g_qlh); cudaGetSymbolAddress((void**)&qll, g_qll);
    cudaGetSymbolAddress((void**)&kvh, g_kvh); cudaGetSymbolAddress((void**)&kvl, g_kvl);
    cudaGetSymbolAddress((void**)&qh, g_qh);   cudaGetSymbolAddress((void**)&ql, g_ql);
    cudaGetSymbolAddress((void**)&kh, g_kh);   cudaGetSymbolAddress((void**)&kl, g_kl);
    cudaGetSymbolAddress((void**)&vf, g_vf);
    cudaGetSymbolAddress((void**)&aof, g_aof);
    cudaGetSymbolAddress((void**)&owf, g_owf);
    cudaGetSymbolAddress((void**)&wqah, g_wqah); cudaGetSymbolAddress((void**)&wqal, g_wqal);
    cudaGetSymbolAddress((void**)&wqbh, g_wqbh); cudaGetSymbolAddress((void**)&wqbl, g_wqbl);
    cudaGetSymbolAddress((void**)&wkvh, g_wkvh); cudaGetSymbolAddress((void**)&wkvl, g_wkvl);
    cudaGetSymbolAddress((void**)&wkbh, g_wkbh); cudaGetSymbolAddress((void**)&wkbl, g_wkbl);
    cudaGetSymbolAddress((void**)&wvbh, g_wvbh); cudaGetSymbolAddress((void**)&wvbl, g_wvbl);

    // one-time stream/event creation (first call is outside graph capture)
    static cudaStream_t s1 = nullptr, s2 = nullptr;
    static cudaEvent_t evF = nullptr, evX = nullptr, evW = nullptr;
    static cudaEvent_t evKV = nullptr, ev1 = nullptr, ev2 = nullptr;
    if (!s1) {
        cudaStreamCreateWithFlags(&s1, cudaStreamNonBlocking);
        cudaStreamCreateWithFlags(&s2, cudaStreamNonBlocking);
        cudaEventCreateWithFlags(&evF, cudaEventDisableTiming);
        cudaEventCreateWithFlags(&evX, cudaEventDisableTiming);
        cudaEventCreateWithFlags(&evW, cudaEventDisableTiming);
        cudaEventCreateWithFlags(&evKV, cudaEventDisableTiming);
        cudaEventCreateWithFlags(&ev1, cudaEventDisableTiming);
        cudaEventCreateWithFlags(&ev2, cudaEventDisableTiming);
        cudaFuncSetAttribute(gemm_mma, cudaFuncAttributeMaxDynamicSharedMemorySize,
                             GEMM_SMEM_BYTES);
        cudaFuncSetAttribute(gemm_f16, cudaFuncAttributeMaxDynamicSharedMemorySize,
                             GEMMH_SMEM_BYTES);
        cudaFuncSetAttribute(flash_mma, cudaFuncAttributeMaxDynamicSharedMemorySize,
                             FLASH_SMEM_BYTES);
    }
    cudaStream_t s0 = 0;   // legacy default stream (capture origin)

    // ---- fork point: all side-stream work hangs off this s0 event --------
    cudaEventRecord(evF, s0);
    cudaStreamWaitEvent(s1, evF, 0);
    cudaStreamWaitEvent(s2, evF, 0);

    // s2: kv/o weight conversions (concurrent with conv(x))
    conv_on(s2, kv_a_w, wkvh, wkvl, KVLATD * DMODEL);
    conv_on(s2, k_b_w, wkbh, wkbl, DMODEL * KVLATD);
    conv_on(s2, v_b_w, wvbh, wvbl, DMODEL * KVLATD);
    conv_f16<<<(DMODEL * DMODEL / 4 + 255) / 256, 256, 0, s2>>>(
        o_w, owf, DMODEL * DMODEL / 4);
    cudaEventRecord(evW, s2);

    // s1: q weight conversions (concurrent with conv(x))
    conv_on(s1, q_a_w, wqah, wqal, QLATD * DMODEL);
    conv_on(s1, q_b_w, wqbh, wqbl, DMODEL * QLATD);

    // s0: shared input conversion
    conv_on(s0, x, xh, xl, TOKENS * DMODEL);
    cudaEventRecord(evX, s0);

    // ---- s1: q chain ----
    cudaStreamWaitEvent(s1, evX, 0);
    gemm_mma<<<dim3(QLATD / 128, TOKENS / 128), 128, GEMM_SMEM_BYTES, s1>>>(
        xh, xl, wqah, wqal, nullptr, qlh, qll, nullptr, TOKENS, QLATD, DMODEL);
    gemm_mma<<<dim3(DMODEL / 128, TOKENS / 128), 128, GEMM_SMEM_BYTES, s1>>>(
        qlh, qll, wqbh, wqbl, q, nullptr, nullptr, nullptr, TOKENS, DMODEL, QLATD);
    norm_rope_kernel<<<TOKENS * NHEADS, 128, 0, s1>>>(q, q_nw, qh, ql);
    cudaEventRecord(ev1, s1);

    // ---- s0: kv chain (needs s2's kv weight convs) ----
    cudaStreamWaitEvent(s0, evW, 0);
    gemm_mma<<<dim3(KVLATD / 128, TOKENS / 128), 128, GEMM_SMEM_BYTES, s0>>>(
        xh, xl, wkvh, wkvl, nullptr, kvh, kvl, nullptr, TOKENS, KVLATD, DMODEL);
    cudaEventRecord(evKV, s0);
    // s2: v_b in parallel with k_b
    cudaStreamWaitEvent(s2, evKV, 0);
    gemm_mma<<<dim3(DMODEL / 128, TOKENS / 128), 128, GEMM_SMEM_BYTES, s2>>>(
        kvh, kvl, wvbh, wvbl, nullptr, nullptr, nullptr, vf, TOKENS, DMODEL, KVLATD);
    cudaEventRecord(ev2, s2);
    // s0: k_b + norm
    gemm_mma<<<dim3(DMODEL / 128, TOKENS / 128), 128, GEMM_SMEM_BYTES, s0>>>(
        kvh, kvl, wkbh, wkbl, k, nullptr, nullptr, nullptr, TOKENS, DMODEL, KVLATD);
    norm_rope_kernel<<<TOKENS * NHEADS, 128, 0, s0>>>(k, k_nw, kh, kl);

    // ---- join: single heavy-first flash launch ----
    cudaStreamWaitEvent(s0, ev1, 0);
    cudaStreamWaitEvent(s0, ev2, 0);
    flash_mma<<<dim3(TSEQ / 128, 2 * NHEADS), 256, FLASH_SMEM_BYTES, s0>>>(
        qh, ql, kh, kl, vf, aof);

    // output projection: single-product fp16 -> fp32 d_out
    gemm_f16<<<dim3(DMODEL / 128, TOKENS / 128), 128, GEMMH_SMEM_BYTES, s0>>>(
        aof, owf, (float*)d_out, TOKENS, DMODEL, DMODEL);
}

// round 16
// speedup vs baseline: 1.0079x; 1.0079x over previous
#include <cuda_runtime.h>
#include <cuda_bf16.h>
#include <cuda_fp16.h>
#include <math.h>
#include <cstdint>

#define TOKENS 4096   // B*T
#define DMODEL 2048   // NH*HD
#define TSEQ   2048
#define NHEADS 16
#define HDIM   128
#define QLATD  1024
#define KVLATD 512

typedef __nv_bfloat16 bf16;

// ---------------- scratch (device globals; no allocation allowed) ----------
__device__ float g_q  [TOKENS * DMODEL];
__device__ float g_k  [TOKENS * DMODEL];
__device__ bf16 g_xh [TOKENS * DMODEL],  g_xl [TOKENS * DMODEL];
__device__ bf16 g_qlh[TOKENS * QLATD],   g_qll[TOKENS * QLATD];
__device__ bf16 g_kvh[TOKENS * KVLATD],  g_kvl[TOKENS * KVLATD];
__device__ bf16 g_qh [TOKENS * DMODEL],  g_ql [TOKENS * DMODEL];
__device__ bf16 g_kh [TOKENS * DMODEL],  g_kl [TOKENS * DMODEL];
__device__ half g_vf [TOKENS * DMODEL];            // V single fp16
__device__ half g_aof[TOKENS * DMODEL];            // attention out, single fp16
__device__ half g_owf[DMODEL * DMODEL];            // o_w single fp16
__device__ bf16 g_wqah[QLATD * DMODEL],  g_wqal[QLATD * DMODEL];
__device__ bf16 g_wqbh[DMODEL * QLATD],  g_wqbl[DMODEL * QLATD];
__device__ bf16 g_wkvh[KVLATD * DMODEL], g_wkvl[KVLATD * DMODEL];
__device__ bf16 g_wkbh[DMODEL * KVLATD], g_wkbl[DMODEL * KVLATD];
__device__ bf16 g_wvbh[DMODEL * KVLATD], g_wvbl[DMODEL * KVLATD];

// ================= helpers (baseline PTX, no "a"-features) =================
__device__ __forceinline__ uint32_t smem_u32(const void* p) {
    uint32_t a;
    asm("{ .reg .u64 t; cvta.to.shared.u64 t, %1; cvt.u32.u64 %0, t; }"
        : "=r"(a) : "l"(p));
    return a;
}
__device__ __forceinline__ float ex2(float x) {
    float y;
    asm("ex2.approx.ftz.f32 %0, %1;" : "=f"(y) : "f"(x));
    return y;
}

#define CP_ASYNC16(sa, gp) \
    asm volatile("cp.async.cg.shared.global [%0], [%1], 16;" :: "r"(sa), "l"(gp))
#define CP_COMMIT() asm volatile("cp.async.commit_group;" ::: "memory")
#define CP_WAIT0()  asm volatile("cp.async.wait_group 0;" ::: "memory")
#define CP_WAIT1()  asm volatile("cp.async.wait_group 1;" ::: "memory")

#define LDM4(r, addr) \
    asm volatile("ldmatrix.sync.aligned.m8n8.x4.shared.b16 {%0,%1,%2,%3}, [%4];" \
                 : "=r"((r)[0]), "=r"((r)[1]), "=r"((r)[2]), "=r"((r)[3]) : "r"(addr))
#define LDM4T(r, addr) \
    asm volatile("ldmatrix.sync.aligned.m8n8.x4.trans.shared.b16 {%0,%1,%2,%3}, [%4];" \
                 : "=r"((r)[0]), "=r"((r)[1]), "=r"((r)[2]), "=r"((r)[3]) : "r"(addr))
#define MMA_BF16(d, a, b) \
    asm volatile("mma.sync.aligned.m16n8k16.row.col.f32.bf16.bf16.f32 " \
                 "{%0,%1,%2,%3}, {%4,%5,%6,%7}, {%8,%9}, {%0,%1,%2,%3};" \
                 : "+f"((d)[0]), "+f"((d)[1]), "+f"((d)[2]), "+f"((d)[3]) \
                 : "r"((a)[0]), "r"((a)[1]), "r"((a)[2]), "r"((a)[3]), \
                   "r"((b)[0]), "r"((b)[1]))
#define MMA_F16(d, a, b) \
    asm volatile("mma.sync.aligned.m16n8k16.row.col.f32.f16.f16.f32 " \
                 "{%0,%1,%2,%3}, {%4,%5,%6,%7}, {%8,%9}, {%0,%1,%2,%3};" \
                 : "+f"((d)[0]), "+f"((d)[1]), "+f"((d)[2]), "+f"((d)[3]) \
                 : "r"((a)[0]), "r"((a)[1]), "r"((a)[2]), "r"((a)[3]), \
                   "r"((b)[0]), "r"((b)[1]))

__device__ __forceinline__ void split2(float v, bf16& h, bf16& l) {
    h = __float2bfloat16_rn(v);
    l = __float2bfloat16_rn(v - __bfloat162float(h));
}
__device__ __forceinline__ void pack_hilo(float a, float b, uint32_t& h, uint32_t& l) {
    bf16 ha, la, hb, lb;
    split2(a, ha, la);
    split2(b, hb, lb);
    __nv_bfloat162 th(ha, hb), tl(la, lb);
    h = *(uint32_t*)&th;
    l = *(uint32_t*)&tl;
}
__device__ __forceinline__ uint32_t pack_h2(float a, float b) {
    __half2 t = __floats2half2_rn(a, b);
    return *(uint32_t*)&t;
}

// ============= 3-term bf16 GEMM: C = (Ah+Al)(Bh+Bl)^T ======================
// 128x128 tile, BK=32, cp.async 2-stage, 4 warps each 64x64.
#define SSTR 40
#define G_ARR  10240
#define G_STG  (4 * G_ARR)
#define GEMM_SMEM_BYTES (2 * G_STG)

__global__ __launch_bounds__(128)
void gemm_mma(const bf16* __restrict__ Ah, const bf16* __restrict__ Al,
              const bf16* __restrict__ Bh, const bf16* __restrict__ Bl,
              float* __restrict__ Cf, bf16* __restrict__ Ch,
              bf16* __restrict__ Cl, half* __restrict__ Cf16,
              int M, int N, int K) {
    extern __shared__ bf16 sg[];
    const uint32_t sb = smem_u32(sg);

    const int tid = threadIdx.x, lane = tid & 31, warp = tid >> 5;
    const int wm = (warp & 1) * 64, wn = (warp >> 1) * 64;
    const int bm = blockIdx.y * 128, bn = blockIdx.x * 128;

    const int lrA = lane & 15, lcA = (lane >> 4) << 3;
    const int l7 = lane & 7;
    const int k8 = ((lane >> 3) & 1) << 3;
    const int n8 = ((lane >> 4) & 1) << 3;

    float c[4][8][4];
#pragma unroll
    for (int i = 0; i < 4; i++)
#pragma unroll
        for (int j = 0; j < 8; j++)
#pragma unroll
            for (int k = 0; k < 4; k++) c[i][j][k] = 0.f;

    auto load_stage = [&](int kt, int s) {
        uint32_t so = sb + (uint32_t)s * G_STG;
#pragma unroll
        for (int i = 0; i < 4; i++) {
            int idx = tid + i * 128;
            int row = idx >> 2, cc = idx & 3;
            size_t gA = (size_t)(bm + row) * K + kt + cc * 8;
            size_t gB = (size_t)(bn + row) * K + kt + cc * 8;
            uint32_t off = (uint32_t)(row * (SSTR * 2) + cc * 16);
            CP_ASYNC16(so + off,             Ah + gA);
            CP_ASYNC16(so + G_ARR + off,     Al + gA);
            CP_ASYNC16(so + 2 * G_ARR + off, Bh + gB);
            CP_ASYNC16(so + 3 * G_ARR + off, Bl + gB);
        }
    };

    const int nkt = K >> 5;
    load_stage(0, 0);
    CP_COMMIT();

    for (int kt = 0; kt < nkt; kt++) {
        if (kt + 1 < nkt) {
            load_stage((kt + 1) << 5, (kt + 1) & 1);
            CP_COMMIT();
            CP_WAIT1();
        } else {
            CP_WAIT0();
        }
        __syncthreads();

        const uint32_t aAh = sb + (uint32_t)(kt & 1) * G_STG;
        const uint32_t aAl = aAh + G_ARR;
        const uint32_t aBh = aAh + 2 * G_ARR;
        const uint32_t aBl = aAh + 3 * G_ARR;

#pragma unroll
        for (int ks = 0; ks < 32; ks += 16) {
            uint32_t bh[8][2], bl[8][2], t[4];
#pragma unroll
            for (int p = 0; p < 4; p++) {
                uint32_t off = (uint32_t)(((wn + p * 16 + n8 + l7) * SSTR + ks + k8) * 2);
                LDM4(t, aBh + off);
                bh[2 * p][0] = t[0]; bh[2 * p][1] = t[1];
                bh[2 * p + 1][0] = t[2]; bh[2 * p + 1][1] = t[3];
                LDM4(t, aBl + off);
                bl[2 * p][0] = t[0]; bl[2 * p][1] = t[1];
                bl[2 * p + 1][0] = t[2]; bl[2 * p + 1][1] = t[3];
            }
#pragma unroll
            for (int mt = 0; mt < 4; mt++) {
                uint32_t off = (uint32_t)(((wm + mt * 16 + lrA) * SSTR + ks + lcA) * 2);
                uint32_t ah[4], al[4];
                LDM4(ah, aAh + off);
                LDM4(al, aAl + off);
#pragma unroll
                for (int nt = 0; nt < 8; nt++) {
                    MMA_BF16(c[mt][nt], ah, bh[nt]);
                    MMA_BF16(c[mt][nt], ah, bl[nt]);
                    MMA_BF16(c[mt][nt], al, bh[nt]);
                }
            }
        }
        __syncthreads();
    }

    const int er = lane >> 2, ec = (lane & 3) << 1;
#pragma unroll
    for (int mt = 0; mt < 4; mt++) {
#pragma unroll
        for (int nt = 0; nt < 8; nt++) {
            size_t r0 = (size_t)(bm + wm + mt * 16 + er);
            int c0 = bn + wn + nt * 8 + ec;
            float v0 = c[mt][nt][0], v1 = c[mt][nt][1];
            float v2 = c[mt][nt][2], v3 = c[mt][nt][3];
            if (Cf) {
                *(float2*)(Cf + r0 * N + c0)       = make_float2(v0, v1);
                *(float2*)(Cf + (r0 + 8) * N + c0) = make_float2(v2, v3);
            }
            if (Ch) {
                uint32_t h01, l01, h23, l23;
                pack_hilo(v0, v1, h01, l01);
                pack_hilo(v2, v3, h23, l23);
                *(uint32_t*)(Ch + r0 * N + c0)       = h01;
                *(uint32_t*)(Ch + (r0 + 8) * N + c0) = h23;
                *(uint32_t*)(Cl + r0 * N + c0)       = l01;
                *(uint32_t*)(Cl + (r0 + 8) * N + c0) = l23;
            }
            if (Cf16) {
                *(uint32_t*)(Cf16 + r0 * N + c0)       = pack_h2(v0, v1);
                *(uint32_t*)(Cf16 + (r0 + 8) * N + c0) = pack_h2(v2, v3);
            }
        }
    }
}

// ============= single-product fp16 GEMM (for output projection) ============
#define H_ARR 10240
#define H_STG (2 * H_ARR)
#define GEMMH_SMEM_BYTES (2 * H_STG)   // 40960

__global__ __launch_bounds__(128)
void gemm_f16(const half* __restrict__ A, const half* __restrict__ B,
              float* __restrict__ Cf, int M, int N, int K) {
    extern __shared__ half sh[];
    const uint32_t sb = smem_u32(sh);

    const int tid = threadIdx.x, lane = tid & 31, warp = tid >> 5;
    const int wm = (warp & 1) * 64, wn = (warp >> 1) * 64;
    const int bm = blockIdx.y * 128, bn = blockIdx.x * 128;

    const int lrA = lane & 15, lcA = (lane >> 4) << 3;
    const int l7 = lane & 7;
    const int k8 = ((lane >> 3) & 1) << 3;
    const int n8 = ((lane >> 4) & 1) << 3;

    float c[4][8][4];
#pragma unroll
    for (int i = 0; i < 4; i++)
#pragma unroll
        for (int j = 0; j < 8; j++)
#pragma unroll
            for (int k = 0; k < 4; k++) c[i][j][k] = 0.f;

    auto load_stage = [&](int kt, int s) {
        uint32_t so = sb + (uint32_t)s * H_STG;
#pragma unroll
        for (int i = 0; i < 4; i++) {
            int idx = tid + i * 128;
            int row = idx >> 2, cc = idx & 3;
            size_t gA = (size_t)(bm + row) * K + kt + cc * 8;
            size_t gB = (size_t)(bn + row) * K + kt + cc * 8;
            uint32_t off = (uint32_t)(row * (SSTR * 2) + cc * 16);
            CP_ASYNC16(so + off,         A + gA);
            CP_ASYNC16(so + H_ARR + off, B + gB);
        }
    };

    const int nkt = K >> 5;
    load_stage(0, 0);
    CP_COMMIT();

    for (int kt = 0; kt < nkt; kt++) {
        if (kt + 1 < nkt) {
            load_stage((kt + 1) << 5, (kt + 1) & 1);
            CP_COMMIT();
            CP_WAIT1();
        } else {
            CP_WAIT0();
        }
        __syncthreads();

        const uint32_t aA = sb + (uint32_t)(kt & 1) * H_STG;
        const uint32_t aB = aA + H_ARR;

#pragma unroll
        for (int ks = 0; ks < 32; ks += 16) {
            uint32_t bh[8][2], t[4];
#pragma unroll
            for (int p = 0; p < 4; p++) {
                uint32_t off = (uint32_t)(((wn + p * 16 + n8 + l7) * SSTR + ks + k8) * 2);
                LDM4(t, aB + off);
                bh[2 * p][0] = t[0]; bh[2 * p][1] = t[1];
                bh[2 * p + 1][0] = t[2]; bh[2 * p + 1][1] = t[3];
            }
#pragma unroll
            for (int mt = 0; mt < 4; mt++) {
                uint32_t off = (uint32_t)(((wm + mt * 16 + lrA) * SSTR + ks + lcA) * 2);
                uint32_t ah[4];
                LDM4(ah, aA + off);
#pragma unroll
                for (int nt = 0; nt < 8; nt++)
                    MMA_F16(c[mt][nt], ah, bh[nt]);
            }
        }
        __syncthreads();
    }

    const int er = lane >> 2, ec = (lane & 3) << 1;
#pragma unroll
    for (int mt = 0; mt < 4; mt++) {
#pragma unroll
        for (int nt = 0; nt < 8; nt++) {
            size_t r0 = (size_t)(bm + wm + mt * 16 + er);
            int c0 = bn + wn + nt * 8 + ec;
            *(float2*)(Cf + r0 * N + c0)       = make_float2(c[mt][nt][0], c[mt][nt][1]);
            *(float2*)(Cf + (r0 + 8) * N + c0) = make_float2(c[mt][nt][2], c[mt][nt][3]);
        }
    }
}

// ---------------- fp32 -> (bf16 hi, bf16 lo) ------------------------------
__global__ __launch_bounds__(256)
void conv_hilo(const float* __restrict__ in, bf16* __restrict__ hi,
               bf16* __restrict__ lo, int n4) {
    int i = blockIdx.x * 256 + threadIdx.x;
    if (i >= n4) return;
    float4 x = ((const float4*)in)[i];
    float v[4] = {x.x, x.y, x.z, x.w};
    bf16 h[4], l[4];
#pragma unroll
    for (int j = 0; j < 4; j++) split2(v[j], h[j], l[j]);
    ((__nv_bfloat162*)hi)[i * 2]     = __nv_bfloat162(h[0], h[1]);
    ((__nv_bfloat162*)hi)[i * 2 + 1] = __nv_bfloat162(h[2], h[3]);
    ((__nv_bfloat162*)lo)[i * 2]     = __nv_bfloat162(l[0], l[1]);
    ((__nv_bfloat162*)lo)[i * 2 + 1] = __nv_bfloat162(l[2], l[3]);
}

// ---------------- fp32 -> fp16 (single) ------------------------------------
__global__ __launch_bounds__(256)
void conv_f16(const float* __restrict__ in, half* __restrict__ out, int n4) {
    int i = blockIdx.x * 256 + threadIdx.x;
    if (i >= n4) return;
    float4 x = ((const float4*)in)[i];
    ((uint32_t*)out)[i * 2]     = pack_h2(x.x, x.y);
    ((uint32_t*)out)[i * 2 + 1] = pack_h2(x.z, x.w);
}

// -------- fused per-head RMSNorm + RoPE, emitting bf16 hi/lo ---------------
__global__ __launch_bounds__(128)
void norm_rope_kernel(const float* __restrict__ X, const float* __restrict__ w,
                      bf16* __restrict__ H, bf16* __restrict__ L) {
    const int blk = blockIdx.x;
    const int token = blk >> 4, h = blk & 15;
    const int t = token & (TSEQ - 1);
    const int i = threadIdx.x;
    const size_t off = (size_t)token * DMODEL + h * HDIM + i;
    float x = X[off];
    float ss = x * x;
#pragma unroll
    for (int o = 16; o; o >>= 1)
        ss += __shfl_xor_sync(0xffffffffu, ss, o);
    __shared__ float sred[4];
    if ((i & 31) == 0) sred[i >> 5] = ss;
    __syncthreads();
    ss = sred[0] + sred[1] + sred[2] + sred[3];
    float rn = rsqrtf(ss * (1.0f / HDIM) + 1e-6f);
    float xn = x * rn * w[i];
    __shared__ float sh[HDIM];
    sh[i] = xn;
    __syncthreads();
    const int f = i & 63;
    float invf = exp2f((float)f * (-13.287712379549449f / 64.0f));
    float ang = (float)t * invf;
    float c, s;
    sincosf(ang, &s, &c);
    float partner = (i < 64) ? -sh[i + 64] : sh[i - 64];
    float out = xn * c + partner * s;
    bf16 hh, ll;
    split2(out, hh, ll);
    H[off] = hh;
    L[off] = ll;
}

// ======== causal flash attention v3: bf16-split S, single-fp16 PV ==========
#define QK_STR 136
#define FQ_H 0
#define FQ_L 34816
#define FKV0 69632
#define FKVS 52224
#define SK_H 0
#define SK_L 17408
#define SV_F 34816
#define FLASH_SMEM_BYTES (69632 + 2 * 52224)   // 174080
#define SCL 0.1275175f     // (1/sqrt(128)) * log2(e)

__global__ __launch_bounds__(256, 1)
void flash_mma(const bf16* __restrict__ Qh, const bf16* __restrict__ Ql,
               const bf16* __restrict__ Kh, const bf16* __restrict__ Kl,
               const half* __restrict__ Vf, half* __restrict__ Of) {
    extern __shared__ char smraw[];
    const uint32_t sb = smem_u32(smraw);

    const int qb = (TSEQ / 128 - 1) - blockIdx.x;   // heavy CTAs first
    const int pair = blockIdx.y;
    const int b = pair >> 4, h = pair & 15;
    const int tid = threadIdx.x, lane = tid & 31, warp = tid >> 5;
    const int wm = warp * 16;
    const int er = lane >> 2, ec = (lane & 3) << 1;
    const int lrA = lane & 15, lcA = (lane >> 4) << 3;
    const int l7 = lane & 7;
    const int k8 = ((lane >> 3) & 1) << 3;
    const int n8 = ((lane >> 4) & 1) << 3;

    const size_t bT = (size_t)b * TSEQ;
    const int hoff = h * HDIM;

#pragma unroll
    for (int i = 0; i < 8; i++) {
        int idx = tid + i * 256;
        int row = idx >> 4, ch = idx & 15;
        size_t g = (bT + qb * 128 + row) * DMODEL + hoff + ch * 8;
        uint32_t off = (uint32_t)(row * (QK_STR * 2) + ch * 16);
        CP_ASYNC16(sb + FQ_H + off, Qh + g);
        CP_ASYNC16(sb + FQ_L + off, Ql + g);
    }
    auto load_kv = [&](int kb, int s) {
        uint32_t so = sb + FKV0 + (uint32_t)s * FKVS;
#pragma unroll
        for (int i = 0; i < 4; i++) {
            int idx = tid + i * 256;
            int row = idx >> 4, ch = idx & 15;
            size_t g = (bT + kb * 64 + row) * DMODEL + hoff + ch * 8;
            uint32_t off = (uint32_t)(row * (QK_STR * 2) + ch * 16);
            CP_ASYNC16(so + SK_H + off, Kh + g);
            CP_ASYNC16(so + SK_L + off, Kl + g);
            CP_ASYNC16(so + SV_F + off, Vf + g);
        }
    };
    load_kv(0, 0);
    CP_COMMIT();

    float o[16][4];
#pragma unroll
    for (int i = 0; i < 16; i++)
#pragma unroll
        for (int j = 0; j < 4; j++) o[i][j] = 0.f;
    float m0 = -1e30f, m1 = -1e30f, l0 = 0.f, l1 = 0.f;

    const int grow_lo = qb * 128 + wm + er;
    const int grow_hi = grow_lo + 8;
    const int row_max = qb * 128 + wm + 15;
    const int nkb = 2 * qb + 2;

    for (int kb = 0; kb < nkb; kb++) {
        if (kb + 1 < nkb) {
            load_kv(kb + 1, (kb + 1) & 1);
            CP_COMMIT();
            CP_WAIT1();
        } else {
            CP_WAIT0();
        }
        __syncthreads();

        if (kb * 64 <= row_max) {   // causal per-warp skip
            const uint32_t sKV = sb + FKV0 + (uint32_t)(kb & 1) * FKVS;
            const uint32_t sKh = sKV + SK_H, sKl = sKV + SK_L;
            const uint32_t sV  = sKV + SV_F;

            float c[8][4];
#pragma unroll
            for (int i = 0; i < 8; i++)
#pragma unroll
                for (int j = 0; j < 4; j++) c[i][j] = 0.f;

#pragma unroll
            for (int ks = 0; ks < 8; ks++) {
                uint32_t ah[4], al[4];
                uint32_t offA = (uint32_t)(((wm + lrA) * QK_STR + ks * 16 + lcA) * 2);
                LDM4(ah, sb + FQ_H + offA);
                LDM4(al, sb + FQ_L + offA);
                uint32_t bh[8][2], bl[8][2], t[4];
#pragma unroll
                for (int p = 0; p < 4; p++) {
                    uint32_t offB = (uint32_t)(((p * 16 + n8 + l7) * QK_STR + ks * 16 + k8) * 2);
                    LDM4(t, sKh + offB);
                    bh[2 * p][0] = t[0]; bh[2 * p][1] = t[1];
                    bh[2 * p + 1][0] = t[2]; bh[2 * p + 1][1] = t[3];
                    LDM4(t, sKl + offB);
                    bl[2 * p][0] = t[0]; bl[2 * p][1] = t[1];
                    bl[2 * p + 1][0] = t[2]; bl[2 * p + 1][1] = t[3];
                }
#pragma unroll
                for (int nt = 0; nt < 8; nt++) {
                    MMA_BF16(c[nt], ah, bh[nt]);
                    MMA_BF16(c[nt], ah, bl[nt]);
                    MMA_BF16(c[nt], al, bh[nt]);
                }
            }

            float mx0 = -1e30f, mx1 = -1e30f;
#pragma unroll
            for (int nt = 0; nt < 8; nt++) {
                int col = kb * 64 + nt * 8 + ec;
#pragma unroll
                for (int j = 0; j < 2; j++) {
                    float s0 = c[nt][j] * SCL;
                    float s1 = c[nt][j + 2] * SCL;
                    if (col + j > grow_lo) s0 = -1e30f;
                    if (col + j > grow_hi) s1 = -1e30f;
                    c[nt][j] = s0; c[nt][j + 2] = s1;
                    mx0 = fmaxf(mx0, s0); mx1 = fmaxf(mx1, s1);
                }
            }
            mx0 = fmaxf(mx0, __shfl_xor_sync(0xffffffffu, mx0, 1));
            mx0 = fmaxf(mx0, __shfl_xor_sync(0xffffffffu, mx0, 2));
            mx1 = fmaxf(mx1, __shfl_xor_sync(0xffffffffu, mx1, 1));
            mx1 = fmaxf(mx1, __shfl_xor_sync(0xffffffffu, mx1, 2));
            float m0n = fmaxf(m0, mx0), m1n = fmaxf(m1, mx1);
            float a0 = ex2(m0 - m0n), a1 = ex2(m1 - m1n);
            m0 = m0n; m1 = m1n;

            float sum0 = 0.f, sum1 = 0.f;
#pragma unroll
            for (int nt = 0; nt < 8; nt++) {
                float p0 = ex2(c[nt][0] - m0n), p1 = ex2(c[nt][1] - m0n);
                float p2 = ex2(c[nt][2] - m1n), p3 = ex2(c[nt][3] - m1n);
                c[nt][0] = p0; c[nt][1] = p1; c[nt][2] = p2; c[nt][3] = p3;
                sum0 += p0 + p1; sum1 += p2 + p3;
            }
            sum0 += __shfl_xor_sync(0xffffffffu, sum0, 1);
            sum0 += __shfl_xor_sync(0xffffffffu, sum0, 2);
            sum1 += __shfl_xor_sync(0xffffffffu, sum1, 1);
            sum1 += __shfl_xor_sync(0xffffffffu, sum1, 2);
            l0 = l0 * a0 + sum0;
            l1 = l1 * a1 + sum1;
            if (a0 != 1.f || a1 != 1.f) {       // skip rescale when max unchanged
#pragma unroll
                for (int nt = 0; nt < 16; nt++) {
                    o[nt][0] *= a0; o[nt][1] *= a0;
                    o[nt][2] *= a1; o[nt][3] *= a1;
                }
            }

            // ---- O += P V : P single fp16 in registers, V single fp16 ----
#pragma unroll
            for (int kk = 0; kk < 4; kk++) {
                uint32_t ph[4];
                ph[0] = pack_h2(c[2 * kk][0],     c[2 * kk][1]);
                ph[1] = pack_h2(c[2 * kk][2],     c[2 * kk][3]);
                ph[2] = pack_h2(c[2 * kk + 1][0], c[2 * kk + 1][1]);
                ph[3] = pack_h2(c[2 * kk + 1][2], c[2 * kk + 1][3]);
#pragma unroll
                for (int p = 0; p < 8; p++) {
                    uint32_t vh[4];
                    uint32_t offV = (uint32_t)(((kk * 16 + l7 + k8) * QK_STR + p * 16 + n8) * 2);
                    LDM4T(vh, sV + offV);
                    uint32_t vh0[2] = {vh[0], vh[1]}, vh1[2] = {vh[2], vh[3]};
                    MMA_F16(o[2 * p], ph, vh0);
                    MMA_F16(o[2 * p + 1], ph, vh1);
                }
            }
        }
        __syncthreads();
    }

    float inv0 = 1.f / l0, inv1 = 1.f / l1;
    size_t tok_lo = (bT + (size_t)grow_lo) * DMODEL + hoff;
    size_t tok_hi = (bT + (size_t)grow_hi) * DMODEL + hoff;
#pragma unroll
    for (int nt = 0; nt < 16; nt++) {
        int col = nt * 8 + ec;
        *(uint32_t*)(Of + tok_lo + col) = pack_h2(o[nt][0] * inv0, o[nt][1] * inv0);
        *(uint32_t*)(Of + tok_hi + col) = pack_h2(o[nt][2] * inv1, o[nt][3] * inv1);
    }
}

// ---------------- launch (multi-stream fork/join, capture-safe) -------------
static inline void conv_on(cudaStream_t st, const float* in, bf16* h, bf16* l, int n) {
    int n4 = n / 4;
    conv_hilo<<<(n4 + 255) / 256, 256, 0, st>>>(in, h, l, n4);
}

extern "C" void kernel_launch(void* const* d_in, const int* in_sizes, int n_in,
                              void* d_out, int out_size) {
    const float* x      = (const float*)d_in[0];
    const float* q_a_w  = (const float*)d_in[2];
    const float* q_b_w  = (const float*)d_in[3];
    const float* kv_a_w = (const float*)d_in[4];
    const float* k_b_w  = (const float*)d_in[5];
    const float* v_b_w  = (const float*)d_in[6];
    const float* o_w    = (const float*)d_in[7];
    const float* q_nw   = (const float*)d_in[8];
    const float* k_nw   = (const float*)d_in[9];

    float *q, *k;
    bf16 *xh, *xl, *qlh, *qll, *kvh, *kvl, *qh, *ql, *kh, *kl;
    half *vf, *aof, *owf;
    bf16 *wqah, *wqal, *wqbh, *wqbl, *wkvh, *wkvl, *wkbh, *wkbl, *wvbh, *wvbl;
    cudaGetSymbolAddress((void**)&q, g_q);     cudaGetSymbolAddress((void**)&k, g_k);
    cudaGetSymbolAddress((void**)&xh, g_xh);   cudaGetSymbolAddress((void**)&xl, g_xl);
    cudaGetSymbolAddress((void**)&qlh, g_qlh); cudaGetSymbolAddress((void**)&qll, g_qll);
    cudaGetSymbolAddress((void**)&kvh, g_kvh); cudaGetSymbolAddress((void**)&kvl, g_kvl);
    cudaGetSymbolAddress((void**)&qh, g_qh);   cudaGetSymbolAddress((void**)&ql, g_ql);
    cudaGetSymbolAddress((void**)&kh, g_kh);   cudaGetSymbolAddress((void**)&kl, g_kl);
    cudaGetSymbolAddress((void**)&vf, g_vf);
    cudaGetSymbolAddress((void**)&aof, g_aof);
    cudaGetSymbolAddress((void**)&owf, g_owf);
    cudaGetSymbolAddress((void**)&wqah, g_wqah); cudaGetSymbolAddress((void**)&wqal, g_wqal);
    cudaGetSymbolAddress((void**)&wqbh, g_wqbh); cudaGetSymbolAddress((void**)&wqbl, g_wqbl);
    cudaGetSymbolAddress((void**)&wkvh, g_wkvh); cudaGetSymbolAddress((void**)&wkvl, g_wkvl);
    cudaGetSymbolAddress((void**)&wkbh, g_wkbh); cudaGetSymbolAddress((void**)&wkbl, g_wkbl);
    cudaGetSymbolAddress((void**)&wvbh, g_wvbh); cudaGetSymbolAddress((void**)&wvbl, g_wvbl);

    // one-time stream/event creation (first call is outside graph capture)
    static cudaStream_t s1 = nullptr, s2 = nullptr;
    static cudaEvent_t evX = nullptr, evKV = nullptr, ev1 = nullptr, ev2 = nullptr;
    if (!s1) {
        cudaStreamCreateWithFlags(&s1, cudaStreamNonBlocking);
        cudaStreamCreateWithFlags(&s2, cudaStreamNonBlocking);
        cudaEventCreateWithFlags(&evX, cudaEventDisableTiming);
        cudaEventCreateWithFlags(&evKV, cudaEventDisableTiming);
        cudaEventCreateWithFlags(&ev1, cudaEventDisableTiming);
        cudaEventCreateWithFlags(&ev2, cudaEventDisableTiming);
        cudaFuncSetAttribute(gemm_mma, cudaFuncAttributeMaxDynamicSharedMemorySize,
                             GEMM_SMEM_BYTES);
        cudaFuncSetAttribute(gemm_f16, cudaFuncAttributeMaxDynamicSharedMemorySize,
                             GEMMH_SMEM_BYTES);
        cudaFuncSetAttribute(flash_mma, cudaFuncAttributeMaxDynamicSharedMemorySize,
                             FLASH_SMEM_BYTES);
    }
    cudaStream_t s0 = 0;   // legacy default stream (capture origin)

    // ---- s0: shared input conversion, then fork ----
    conv_on(s0, x, xh, xl, TOKENS * DMODEL);
    cudaEventRecord(evX, s0);

    // ---- s1: q chain ----
    cudaStreamWaitEvent(s1, evX, 0);
    conv_on(s1, q_a_w, wqah, wqal, QLATD * DMODEL);
    conv_on(s1, q_b_w, wqbh, wqbl, DMODEL * QLATD);
    gemm_mma<<<dim3(QLATD / 128, TOKENS / 128), 128, GEMM_SMEM_BYTES, s1>>>(
        xh, xl, wqah, wqal, nullptr, qlh, qll, nullptr, TOKENS, QLATD, DMODEL);
    gemm_mma<<<dim3(DMODEL / 128, TOKENS / 128), 128, GEMM_SMEM_BYTES, s1>>>(
        qlh, qll, wqbh, wqbl, q, nullptr, nullptr, nullptr, TOKENS, DMODEL, QLATD);
    norm_rope_kernel<<<TOKENS * NHEADS, 128, 0, s1>>>(q, q_nw, qh, ql);
    cudaEventRecord(ev1, s1);

    // ---- s0: kv chain ----
    conv_on(s0, kv_a_w, wkvh, wkvl, KVLATD * DMODEL);
    conv_on(s0, k_b_w, wkbh, wkbl, DMODEL * KVLATD);
    conv_on(s0, v_b_w, wvbh, wvbl, DMODEL * KVLATD);
    conv_f16<<<(DMODEL * DMODEL / 4 + 255) / 256, 256, 0, s0>>>(
        o_w, owf, DMODEL * DMODEL / 4);
    gemm_mma<<<dim3(KVLATD / 128, TOKENS / 128), 128, GEMM_SMEM_BYTES, s0>>>(
        xh, xl, wkvh, wkvl, nullptr, kvh, kvl, nullptr, TOKENS, KVLATD, DMODEL);
    cudaEventRecord(evKV, s0);
    // s2: v_b in parallel with k_b
    cudaStreamWaitEvent(s2, evKV, 0);
    gemm_mma<<<dim3(DMODEL / 128, TOKENS / 128), 128, GEMM_SMEM_BYTES, s2>>>(
        kvh, kvl, wvbh, wvbl, nullptr, nullptr, nullptr, vf, TOKENS, DMODEL, KVLATD);
    cudaEventRecord(ev2, s2);
    // s0: k_b + norm
    gemm_mma<<<dim3(DMODEL / 128, TOKENS / 128), 128, GEMM_SMEM_BYTES, s0>>>(
        kvh, kvl, wkbh, wkbl, k, nullptr, nullptr, nullptr, TOKENS, DMODEL, KVLATD);
    norm_rope_kernel<<<TOKENS * NHEADS, 128, 0, s0>>>(k, k_nw, kh, kl);

    // ---- join: flash needs q chain (ev1) and v_b (ev2); k chain is on s0 ----
    cudaStreamWaitEvent(s0, ev1, 0);
    cudaStreamWaitEvent(s0, ev2, 0);
    flash_mma<<<dim3(TSEQ / 128, 2 * NHEADS), 256, FLASH_SMEM_BYTES, s0>>>(
        qh, ql, kh, kl, vf, aof);

    // output projection: single-product fp16 -> fp32 d_out
    gemm_f16<<<dim3(DMODEL / 128, TOKENS / 128), 128, GEMMH_SMEM_BYTES, s0>>>(
        aof, owf, (float*)d_out, TOKENS, DMODEL, DMODEL);
}

// round 17
// speedup vs baseline: 1.5383x; 1.5262x over previous
#include <cuda_runtime.h>
#include <cuda_bf16.h>
#include <cuda_fp16.h>
#include <math.h>
#include <cstdint>

#define TOKENS 4096   // B*T
#define DMODEL 2048   // NH*HD
#define TSEQ   2048
#define NHEADS 16
#define HDIM   128
#define QLATD  1024
#define KVLATD 512

typedef __nv_bfloat16 bf16;

// ---------------- scratch (device globals; no allocation allowed) ----------
__device__ float g_q  [TOKENS * DMODEL];
__device__ float g_k  [TOKENS * DMODEL];
__device__ bf16 g_xh [TOKENS * DMODEL],  g_xl [TOKENS * DMODEL];
__device__ bf16 g_qlh[TOKENS * QLATD],   g_qll[TOKENS * QLATD];
__device__ bf16 g_kvh[TOKENS * KVLATD],  g_kvl[TOKENS * KVLATD];
__device__ bf16 g_qh [TOKENS * DMODEL],  g_ql [TOKENS * DMODEL];
__device__ bf16 g_kh [TOKENS * DMODEL],  g_kl [TOKENS * DMODEL];
__device__ half g_vf [TOKENS * DMODEL];            // V single fp16
__device__ half g_aof[TOKENS * DMODEL];            // attention out, single fp16
__device__ half g_owf[DMODEL * DMODEL];            // o_w single fp16
__device__ bf16 g_wqah[QLATD * DMODEL],  g_wqal[QLATD * DMODEL];
__device__ bf16 g_wqbh[DMODEL * QLATD],  g_wqbl[DMODEL * QLATD];
__device__ bf16 g_wkvh[KVLATD * DMODEL], g_wkvl[KVLATD * DMODEL];
__device__ bf16 g_wkbh[DMODEL * KVLATD], g_wkbl[DMODEL * KVLATD];
__device__ bf16 g_wvbh[DMODEL * KVLATD], g_wvbl[DMODEL * KVLATD];

// ================= helpers (baseline PTX, no "a"-features) =================
__device__ __forceinline__ uint32_t smem_u32(const void* p) {
    uint32_t a;
    asm("{ .reg .u64 t; cvta.to.shared.u64 t, %1; cvt.u32.u64 %0, t; }"
        : "=r"(a) : "l"(p));
    return a;
}
__device__ __forceinline__ float ex2(float x) {
    float y;
    asm("ex2.approx.ftz.f32 %0, %1;" : "=f"(y) : "f"(x));
    return y;
}

#define CP_ASYNC16(sa, gp) \
    asm volatile("cp.async.cg.shared.global [%0], [%1], 16;" :: "r"(sa), "l"(gp))
#define CP_COMMIT() asm volatile("cp.async.commit_group;" ::: "memory")
#define CP_WAIT0()  asm volatile("cp.async.wait_group 0;" ::: "memory")
#define CP_WAIT1()  asm volatile("cp.async.wait_group 1;" ::: "memory")

#define LDM4(r, addr) \
    asm volatile("ldmatrix.sync.aligned.m8n8.x4.shared.b16 {%0,%1,%2,%3}, [%4];" \
                 : "=r"((r)[0]), "=r"((r)[1]), "=r"((r)[2]), "=r"((r)[3]) : "r"(addr))
#define LDM4T(r, addr) \
    asm volatile("ldmatrix.sync.aligned.m8n8.x4.trans.shared.b16 {%0,%1,%2,%3}, [%4];" \
                 : "=r"((r)[0]), "=r"((r)[1]), "=r"((r)[2]), "=r"((r)[3]) : "r"(addr))
#define MMA_BF16(d, a, b) \
    asm volatile("mma.sync.aligned.m16n8k16.row.col.f32.bf16.bf16.f32 " \
                 "{%0,%1,%2,%3}, {%4,%5,%6,%7}, {%8,%9}, {%0,%1,%2,%3};" \
                 : "+f"((d)[0]), "+f"((d)[1]), "+f"((d)[2]), "+f"((d)[3]) \
                 : "r"((a)[0]), "r"((a)[1]), "r"((a)[2]), "r"((a)[3]), \
                   "r"((b)[0]), "r"((b)[1]))
#define MMA_F16(d, a, b) \
    asm volatile("mma.sync.aligned.m16n8k16.row.col.f32.f16.f16.f32 " \
                 "{%0,%1,%2,%3}, {%4,%5,%6,%7}, {%8,%9}, {%0,%1,%2,%3};" \
                 : "+f"((d)[0]), "+f"((d)[1]), "+f"((d)[2]), "+f"((d)[3]) \
                 : "r"((a)[0]), "r"((a)[1]), "r"((a)[2]), "r"((a)[3]), \
                   "r"((b)[0]), "r"((b)[1]))

__device__ __forceinline__ void split2(float v, bf16& h, bf16& l) {
    h = __float2bfloat16_rn(v);
    l = __float2bfloat16_rn(v - __bfloat162float(h));
}
__device__ __forceinline__ void pack_hilo(float a, float b, uint32_t& h, uint32_t& l) {
    bf16 ha, la, hb, lb;
    split2(a, ha, la);
    split2(b, hb, lb);
    __nv_bfloat162 th(ha, hb), tl(la, lb);
    h = *(uint32_t*)&th;
    l = *(uint32_t*)&tl;
}
__device__ __forceinline__ uint32_t pack_h2(float a, float b) {
    __half2 t = __floats2half2_rn(a, b);
    return *(uint32_t*)&t;
}

// ============= 3-term bf16 GEMM: C = (Ah+Al)(Bh+Bl)^T ======================
// 128x128 tile, BK=32, cp.async 2-stage, 4 warps each 64x64.
#define SSTR 40
#define G_ARR  10240
#define G_STG  (4 * G_ARR)
#define GEMM_SMEM_BYTES (2 * G_STG)

__global__ __launch_bounds__(128)
void gemm_mma(const bf16* __restrict__ Ah, const bf16* __restrict__ Al,
              const bf16* __restrict__ Bh, const bf16* __restrict__ Bl,
              float* __restrict__ Cf, bf16* __restrict__ Ch,
              bf16* __restrict__ Cl, half* __restrict__ Cf16,
              int M, int N, int K) {
    extern __shared__ bf16 sg[];
    const uint32_t sb = smem_u32(sg);

    const int tid = threadIdx.x, lane = tid & 31, warp = tid >> 5;
    const int wm = (warp & 1) * 64, wn = (warp >> 1) * 64;
    const int bm = blockIdx.y * 128, bn = blockIdx.x * 128;

    const int lrA = lane & 15, lcA = (lane >> 4) << 3;
    const int l7 = lane & 7;
    const int k8 = ((lane >> 3) & 1) << 3;
    const int n8 = ((lane >> 4) & 1) << 3;

    float c[4][8][4];
#pragma unroll
    for (int i = 0; i < 4; i++)
#pragma unroll
        for (int j = 0; j < 8; j++)
#pragma unroll
            for (int k = 0; k < 4; k++) c[i][j][k] = 0.f;

    auto load_stage = [&](int kt, int s) {
        uint32_t so = sb + (uint32_t)s * G_STG;
#pragma unroll
        for (int i = 0; i < 4; i++) {
            int idx = tid + i * 128;
            int row = idx >> 2, cc = idx & 3;
            size_t gA = (size_t)(bm + row) * K + kt + cc * 8;
            size_t gB = (size_t)(bn + row) * K + kt + cc * 8;
            uint32_t off = (uint32_t)(row * (SSTR * 2) + cc * 16);
            CP_ASYNC16(so + off,             Ah + gA);
            CP_ASYNC16(so + G_ARR + off,     Al + gA);
            CP_ASYNC16(so + 2 * G_ARR + off, Bh + gB);
            CP_ASYNC16(so + 3 * G_ARR + off, Bl + gB);
        }
    };

    const int nkt = K >> 5;
    load_stage(0, 0);
    CP_COMMIT();

    for (int kt = 0; kt < nkt; kt++) {
        if (kt + 1 < nkt) {
            load_stage((kt + 1) << 5, (kt + 1) & 1);
            CP_COMMIT();
            CP_WAIT1();
        } else {
            CP_WAIT0();
        }
        __syncthreads();

        const uint32_t aAh = sb + (uint32_t)(kt & 1) * G_STG;
        const uint32_t aAl = aAh + G_ARR;
        const uint32_t aBh = aAh + 2 * G_ARR;
        const uint32_t aBl = aAh + 3 * G_ARR;

#pragma unroll
        for (int ks = 0; ks < 32; ks += 16) {
            uint32_t bh[8][2], bl[8][2], t[4];
#pragma unroll
            for (int p = 0; p < 4; p++) {
                uint32_t off = (uint32_t)(((wn + p * 16 + n8 + l7) * SSTR + ks + k8) * 2);
                LDM4(t, aBh + off);
                bh[2 * p][0] = t[0]; bh[2 * p][1] = t[1];
                bh[2 * p + 1][0] = t[2]; bh[2 * p + 1][1] = t[3];
                LDM4(t, aBl + off);
                bl[2 * p][0] = t[0]; bl[2 * p][1] = t[1];
                bl[2 * p + 1][0] = t[2]; bl[2 * p + 1][1] = t[3];
            }
#pragma unroll
            for (int mt = 0; mt < 4; mt++) {
                uint32_t off = (uint32_t)(((wm + mt * 16 + lrA) * SSTR + ks + lcA) * 2);
                uint32_t ah[4], al[4];
                LDM4(ah, aAh + off);
                LDM4(al, aAl + off);
#pragma unroll
                for (int nt = 0; nt < 8; nt++) {
                    MMA_BF16(c[mt][nt], ah, bh[nt]);
                    MMA_BF16(c[mt][nt], ah, bl[nt]);
                    MMA_BF16(c[mt][nt], al, bh[nt]);
                }
            }
        }
        __syncthreads();
    }

    const int er = lane >> 2, ec = (lane & 3) << 1;
#pragma unroll
    for (int mt = 0; mt < 4; mt++) {
#pragma unroll
        for (int nt = 0; nt < 8; nt++) {
            size_t r0 = (size_t)(bm + wm + mt * 16 + er);
            int c0 = bn + wn + nt * 8 + ec;
            float v0 = c[mt][nt][0], v1 = c[mt][nt][1];
            float v2 = c[mt][nt][2], v3 = c[mt][nt][3];
            if (Cf) {
                *(float2*)(Cf + r0 * N + c0)       = make_float2(v0, v1);
                *(float2*)(Cf + (r0 + 8) * N + c0) = make_float2(v2, v3);
            }
            if (Ch) {
                uint32_t h01, l01, h23, l23;
                pack_hilo(v0, v1, h01, l01);
                pack_hilo(v2, v3, h23, l23);
                *(uint32_t*)(Ch + r0 * N + c0)       = h01;
                *(uint32_t*)(Ch + (r0 + 8) * N + c0) = h23;
                *(uint32_t*)(Cl + r0 * N + c0)       = l01;
                *(uint32_t*)(Cl + (r0 + 8) * N + c0) = l23;
            }
            if (Cf16) {
                *(uint32_t*)(Cf16 + r0 * N + c0)       = pack_h2(v0, v1);
                *(uint32_t*)(Cf16 + (r0 + 8) * N + c0) = pack_h2(v2, v3);
            }
        }
    }
}

// ============= single-product fp16 GEMM (for output projection) ============
#define H_ARR 10240
#define H_STG (2 * H_ARR)
#define GEMMH_SMEM_BYTES (2 * H_STG)   // 40960

__global__ __launch_bounds__(128)
void gemm_f16(const half* __restrict__ A, const half* __restrict__ B,
              float* __restrict__ Cf, int M, int N, int K) {
    extern __shared__ half sh[];
    const uint32_t sb = smem_u32(sh);

    const int tid = threadIdx.x, lane = tid & 31, warp = tid >> 5;
    const int wm = (warp & 1) * 64, wn = (warp >> 1) * 64;
    const int bm = blockIdx.y * 128, bn = blockIdx.x * 128;

    const int lrA = lane & 15, lcA = (lane >> 4) << 3;
    const int l7 = lane & 7;
    const int k8 = ((lane >> 3) & 1) << 3;
    const int n8 = ((lane >> 4) & 1) << 3;

    float c[4][8][4];
#pragma unroll
    for (int i = 0; i < 4; i++)
#pragma unroll
        for (int j = 0; j < 8; j++)
#pragma unroll
            for (int k = 0; k < 4; k++) c[i][j][k] = 0.f;

    auto load_stage = [&](int kt, int s) {
        uint32_t so = sb + (uint32_t)s * H_STG;
#pragma unroll
        for (int i = 0; i < 4; i++) {
            int idx = tid + i * 128;
            int row = idx >> 2, cc = idx & 3;
            size_t gA = (size_t)(bm + row) * K + kt + cc * 8;
            size_t gB = (size_t)(bn + row) * K + kt + cc * 8;
            uint32_t off = (uint32_t)(row * (SSTR * 2) + cc * 16);
            CP_ASYNC16(so + off,         A + gA);
            CP_ASYNC16(so + H_ARR + off, B + gB);
        }
    };

    const int nkt = K >> 5;
    load_stage(0, 0);
    CP_COMMIT();

    for (int kt = 0; kt < nkt; kt++) {
        if (kt + 1 < nkt) {
            load_stage((kt + 1) << 5, (kt + 1) & 1);
            CP_COMMIT();
            CP_WAIT1();
        } else {
            CP_WAIT0();
        }
        __syncthreads();

        const uint32_t aA = sb + (uint32_t)(kt & 1) * H_STG;
        const uint32_t aB = aA + H_ARR;

#pragma unroll
        for (int ks = 0; ks < 32; ks += 16) {
            uint32_t bh[8][2], t[4];
#pragma unroll
            for (int p = 0; p < 4; p++) {
                uint32_t off = (uint32_t)(((wn + p * 16 + n8 + l7) * SSTR + ks + k8) * 2);
                LDM4(t, aB + off);
                bh[2 * p][0] = t[0]; bh[2 * p][1] = t[1];
                bh[2 * p + 1][0] = t[2]; bh[2 * p + 1][1] = t[3];
            }
#pragma unroll
            for (int mt = 0; mt < 4; mt++) {
                uint32_t off = (uint32_t)(((wm + mt * 16 + lrA) * SSTR + ks + lcA) * 2);
                uint32_t ah[4];
                LDM4(ah, aA + off);
#pragma unroll
                for (int nt = 0; nt < 8; nt++)
                    MMA_F16(c[mt][nt], ah, bh[nt]);
            }
        }
        __syncthreads();
    }

    const int er = lane >> 2, ec = (lane & 3) << 1;
#pragma unroll
    for (int mt = 0; mt < 4; mt++) {
#pragma unroll
        for (int nt = 0; nt < 8; nt++) {
            size_t r0 = (size_t)(bm + wm + mt * 16 + er);
            int c0 = bn + wn + nt * 8 + ec;
            *(float2*)(Cf + r0 * N + c0)       = make_float2(c[mt][nt][0], c[mt][nt][1]);
            *(float2*)(Cf + (r0 + 8) * N + c0) = make_float2(c[mt][nt][2], c[mt][nt][3]);
        }
    }
}

// ---------------- fp32 -> (bf16 hi, bf16 lo) ------------------------------
__global__ __launch_bounds__(256)
void conv_hilo(const float* __restrict__ in, bf16* __restrict__ hi,
               bf16* __restrict__ lo, int n4) {
    int i = blockIdx.x * 256 + threadIdx.x;
    if (i >= n4) return;
    float4 x = ((const float4*)in)[i];
    float v[4] = {x.x, x.y, x.z, x.w};
    bf16 h[4], l[4];
#pragma unroll
    for (int j = 0; j < 4; j++) split2(v[j], h[j], l[j]);
    ((__nv_bfloat162*)hi)[i * 2]     = __nv_bfloat162(h[0], h[1]);
    ((__nv_bfloat162*)hi)[i * 2 + 1] = __nv_bfloat162(h[2], h[3]);
    ((__nv_bfloat162*)lo)[i * 2]     = __nv_bfloat162(l[0], l[1]);
    ((__nv_bfloat162*)lo)[i * 2 + 1] = __nv_bfloat162(l[2], l[3]);
}

// ---------------- fp32 -> fp16 (single) ------------------------------------
__global__ __launch_bounds__(256)
void conv_f16(const float* __restrict__ in, half* __restrict__ out, int n4) {
    int i = blockIdx.x * 256 + threadIdx.x;
    if (i >= n4) return;
    float4 x = ((const float4*)in)[i];
    ((uint32_t*)out)[i * 2]     = pack_h2(x.x, x.y);
    ((uint32_t*)out)[i * 2 + 1] = pack_h2(x.z, x.w);
}

// -------- fused per-head RMSNorm + RoPE, emitting bf16 hi/lo ---------------
__global__ __launch_bounds__(128)
void norm_rope_kernel(const float* __restrict__ X, const float* __restrict__ w,
                      bf16* __restrict__ H, bf16* __restrict__ L) {
    const int blk = blockIdx.x;
    const int token = blk >> 4, h = blk & 15;
    const int t = token & (TSEQ - 1);
    const int i = threadIdx.x;
    const size_t off = (size_t)token * DMODEL + h * HDIM + i;
    float x = X[off];
    float ss = x * x;
#pragma unroll
    for (int o = 16; o; o >>= 1)
        ss += __shfl_xor_sync(0xffffffffu, ss, o);
    __shared__ float sred[4];
    if ((i & 31) == 0) sred[i >> 5] = ss;
    __syncthreads();
    ss = sred[0] + sred[1] + sred[2] + sred[3];
    float rn = rsqrtf(ss * (1.0f / HDIM) + 1e-6f);
    float xn = x * rn * w[i];
    __shared__ float sh[HDIM];
    sh[i] = xn;
    __syncthreads();
    const int f = i & 63;
    float invf = exp2f((float)f * (-13.287712379549449f / 64.0f));
    float ang = (float)t * invf;
    float c, s;
    sincosf(ang, &s, &c);
    float partner = (i < 64) ? -sh[i + 64] : sh[i - 64];
    float out = xn * c + partner * s;
    bf16 hh, ll;
    split2(out, hh, ll);
    H[off] = hh;
    L[off] = ll;
}

// ======== causal flash attention v3: bf16-split S, single-fp16 PV ==========
#define QK_STR 136
#define FQ_H 0
#define FQ_L 34816
#define FKV0 69632
#define FKVS 52224
#define SK_H 0
#define SK_L 17408
#define SV_F 34816
#define FLASH_SMEM_BYTES (69632 + 2 * 52224)   // 174080
#define SCL 0.1275175f     // (1/sqrt(128)) * log2(e)

__global__ __launch_bounds__(256, 1)
void flash_mma(const bf16* __restrict__ Qh, const bf16* __restrict__ Ql,
               const bf16* __restrict__ Kh, const bf16* __restrict__ Kl,
               const half* __restrict__ Vf, half* __restrict__ Of) {
    extern __shared__ char smraw[];
    const uint32_t sb = smem_u32(smraw);

    const int qb = (TSEQ / 128 - 1) - blockIdx.x;   // heavy CTAs first
    const int pair = blockIdx.y;
    const int b = pair >> 4, h = pair & 15;
    const int tid = threadIdx.x, lane = tid & 31, warp = tid >> 5;
    const int wm = warp * 16;
    const int er = lane >> 2, ec = (lane & 3) << 1;
    const int lrA = lane & 15, lcA = (lane >> 4) << 3;
    const int l7 = lane & 7;
    const int k8 = ((lane >> 3) & 1) << 3;
    const int n8 = ((lane >> 4) & 1) << 3;

    const size_t bT = (size_t)b * TSEQ;
    const int hoff = h * HDIM;

#pragma unroll
    for (int i = 0; i < 8; i++) {
        int idx = tid + i * 256;
        int row = idx >> 4, ch = idx & 15;
        size_t g = (bT + qb * 128 + row) * DMODEL + hoff + ch * 8;
        uint32_t off = (uint32_t)(row * (QK_STR * 2) + ch * 16);
        CP_ASYNC16(sb + FQ_H + off, Qh + g);
        CP_ASYNC16(sb + FQ_L + off, Ql + g);
    }
    auto load_kv = [&](int kb, int s) {
        uint32_t so = sb + FKV0 + (uint32_t)s * FKVS;
#pragma unroll
        for (int i = 0; i < 4; i++) {
            int idx = tid + i * 256;
            int row = idx >> 4, ch = idx & 15;
            size_t g = (bT + kb * 64 + row) * DMODEL + hoff + ch * 8;
            uint32_t off = (uint32_t)(row * (QK_STR * 2) + ch * 16);
            CP_ASYNC16(so + SK_H + off, Kh + g);
            CP_ASYNC16(so + SK_L + off, Kl + g);
            CP_ASYNC16(so + SV_F + off, Vf + g);
        }
    };
    load_kv(0, 0);
    CP_COMMIT();

    float o[16][4];
#pragma unroll
    for (int i = 0; i < 16; i++)
#pragma unroll
        for (int j = 0; j < 4; j++) o[i][j] = 0.f;
    float m0 = -1e30f, m1 = -1e30f, l0 = 0.f, l1 = 0.f;

    const int grow_lo = qb * 128 + wm + er;
    const int grow_hi = grow_lo + 8;
    const int row_max = qb * 128 + wm + 15;
    const int nkb = 2 * qb + 2;

    for (int kb = 0; kb < nkb; kb++) {
        if (kb + 1 < nkb) {
            load_kv(kb + 1, (kb + 1) & 1);
            CP_COMMIT();
            CP_WAIT1();
        } else {
            CP_WAIT0();
        }
        __syncthreads();

        if (kb * 64 <= row_max) {   // causal per-warp skip
            const uint32_t sKV = sb + FKV0 + (uint32_t)(kb & 1) * FKVS;
            const uint32_t sKh = sKV + SK_H, sKl = sKV + SK_L;
            const uint32_t sV  = sKV + SV_F;

            float c[8][4];
#pragma unroll
            for (int i = 0; i < 8; i++)
#pragma unroll
                for (int j = 0; j < 4; j++) c[i][j] = 0.f;

#pragma unroll
            for (int ks = 0; ks < 8; ks++) {
                uint32_t ah[4], al[4];
                uint32_t offA = (uint32_t)(((wm + lrA) * QK_STR + ks * 16 + lcA) * 2);
                LDM4(ah, sb + FQ_H + offA);
                LDM4(al, sb + FQ_L + offA);
                uint32_t bh[8][2], bl[8][2], t[4];
#pragma unroll
                for (int p = 0; p < 4; p++) {
                    uint32_t offB = (uint32_t)(((p * 16 + n8 + l7) * QK_STR + ks * 16 + k8) * 2);
                    LDM4(t, sKh + offB);
                    bh[2 * p][0] = t[0]; bh[2 * p][1] = t[1];
                    bh[2 * p + 1][0] = t[2]; bh[2 * p + 1][1] = t[3];
                    LDM4(t, sKl + offB);
                    bl[2 * p][0] = t[0]; bl[2 * p][1] = t[1];
                    bl[2 * p + 1][0] = t[2]; bl[2 * p + 1][1] = t[3];
                }
#pragma unroll
                for (int nt = 0; nt < 8; nt++) {
                    MMA_BF16(c[nt], ah, bh[nt]);
                    MMA_BF16(c[nt], ah, bl[nt]);
                    MMA_BF16(c[nt], al, bh[nt]);
                }
            }

            float mx0 = -1e30f, mx1 = -1e30f;
#pragma unroll
            for (int nt = 0; nt < 8; nt++) {
                int col = kb * 64 + nt * 8 + ec;
#pragma unroll
                for (int j = 0; j < 2; j++) {
                    float s0 = c[nt][j] * SCL;
                    float s1 = c[nt][j + 2] * SCL;
                    if (col + j > grow_lo) s0 = -1e30f;
                    if (col + j > grow_hi) s1 = -1e30f;
                    c[nt][j] = s0; c[nt][j + 2] = s1;
                    mx0 = fmaxf(mx0, s0); mx1 = fmaxf(mx1, s1);
                }
            }
            mx0 = fmaxf(mx0, __shfl_xor_sync(0xffffffffu, mx0, 1));
            mx0 = fmaxf(mx0, __shfl_xor_sync(0xffffffffu, mx0, 2));
            mx1 = fmaxf(mx1, __shfl_xor_sync(0xffffffffu, mx1, 1));
            mx1 = fmaxf(mx1, __shfl_xor_sync(0xffffffffu, mx1, 2));
            float m0n = fmaxf(m0, mx0), m1n = fmaxf(m1, mx1);
            float a0 = ex2(m0 - m0n), a1 = ex2(m1 - m1n);
            m0 = m0n; m1 = m1n;

            float sum0 = 0.f, sum1 = 0.f;
#pragma unroll
            for (int nt = 0; nt < 8; nt++) {
                float p0 = ex2(c[nt][0] - m0n), p1 = ex2(c[nt][1] - m0n);
                float p2 = ex2(c[nt][2] - m1n), p3 = ex2(c[nt][3] - m1n);
                c[nt][0] = p0; c[nt][1] = p1; c[nt][2] = p2; c[nt][3] = p3;
                sum0 += p0 + p1; sum1 += p2 + p3;
            }
            sum0 += __shfl_xor_sync(0xffffffffu, sum0, 1);
            sum0 += __shfl_xor_sync(0xffffffffu, sum0, 2);
            sum1 += __shfl_xor_sync(0xffffffffu, sum1, 1);
            sum1 += __shfl_xor_sync(0xffffffffu, sum1, 2);
            l0 = l0 * a0 + sum0;
            l1 = l1 * a1 + sum1;
            if (a0 != 1.f || a1 != 1.f) {       // skip rescale when max unchanged
#pragma unroll
                for (int nt = 0; nt < 16; nt++) {
                    o[nt][0] *= a0; o[nt][1] *= a0;
                    o[nt][2] *= a1; o[nt][3] *= a1;
                }
            }

            // ---- O += P V : P single fp16 in registers, V single fp16 ----
#pragma unroll
            for (int kk = 0; kk < 4; kk++) {
                uint32_t ph[4];
                ph[0] = pack_h2(c[2 * kk][0],     c[2 * kk][1]);
                ph[1] = pack_h2(c[2 * kk][2],     c[2 * kk][3]);
                ph[2] = pack_h2(c[2 * kk + 1][0], c[2 * kk + 1][1]);
                ph[3] = pack_h2(c[2 * kk + 1][2], c[2 * kk + 1][3]);
#pragma unroll
                for (int p = 0; p < 8; p++) {
                    uint32_t vh[4];
                    uint32_t offV = (uint32_t)(((kk * 16 + l7 + k8) * QK_STR + p * 16 + n8) * 2);
                    LDM4T(vh, sV + offV);
                    uint32_t vh0[2] = {vh[0], vh[1]}, vh1[2] = {vh[2], vh[3]};
                    MMA_F16(o[2 * p], ph, vh0);
                    MMA_F16(o[2 * p + 1], ph, vh1);
                }
            }
        }
        __syncthreads();
    }

    float inv0 = 1.f / l0, inv1 = 1.f / l1;
    size_t tok_lo = (bT + (size_t)grow_lo) * DMODEL + hoff;
    size_t tok_hi = (bT + (size_t)grow_hi) * DMODEL + hoff;
#pragma unroll
    for (int nt = 0; nt < 16; nt++) {
        int col = nt * 8 + ec;
        *(uint32_t*)(Of + tok_lo + col) = pack_h2(o[nt][0] * inv0, o[nt][1] * inv0);
        *(uint32_t*)(Of + tok_hi + col) = pack_h2(o[nt][2] * inv1, o[nt][3] * inv1);
    }
}

// ---------------- launch (multi-stream fork/join, capture-safe) -------------
static inline void conv_on(cudaStream_t st, const float* in, bf16* h, bf16* l, int n) {
    int n4 = n / 4;
    conv_hilo<<<(n4 + 255) / 256, 256, 0, st>>>(in, h, l, n4);
}

extern "C" void kernel_launch(void* const* d_in, const int* in_sizes, int n_in,
                              void* d_out, int out_size) {
    const float* x      = (const float*)d_in[0];
    const float* q_a_w  = (const float*)d_in[2];
    const float* q_b_w  = (const float*)d_in[3];
    const float* kv_a_w = (const float*)d_in[4];
    const float* k_b_w  = (const float*)d_in[5];
    const float* v_b_w  = (const float*)d_in[6];
    const float* o_w    = (const float*)d_in[7];
    const float* q_nw   = (const float*)d_in[8];
    const float* k_nw   = (const float*)d_in[9];

    float *q, *k;
    bf16 *xh, *xl, *qlh, *qll, *kvh, *kvl, *qh, *ql, *kh, *kl;
    half *vf, *aof, *owf;
    bf16 *wqah, *wqal, *wqbh, *wqbl, *wkvh, *wkvl, *wkbh, *wkbl, *wvbh, *wvbl;
    cudaGetSymbolAddress((void**)&q, g_q);     cudaGetSymbolAddress((void**)&k, g_k);
    cudaGetSymbolAddress((void**)&xh, g_xh);   cudaGetSymbolAddress((void**)&xl, g_xl);
    cudaGetSymbolAddress((void**)&qlh, g_qlh); cudaGetSymbolAddress((void**)&qll, g_qll);
    cudaGetSymbolAddress((void**)&kvh, g_kvh); cudaGetSymbolAddress((void**)&kvl, g_kvl);
    cudaGetSymbolAddress((void**)&qh, g_qh);   cudaGetSymbolAddress((void**)&ql, g_ql);
    cudaGetSymbolAddress((void**)&kh, g_kh);   cudaGetSymbolAddress((void**)&kl, g_kl);
    cudaGetSymbolAddress((void**)&vf, g_vf);
    cudaGetSymbolAddress((void**)&aof, g_aof);
    cudaGetSymbolAddress((void**)&owf, g_owf);
    cudaGetSymbolAddress((void**)&wqah, g_wqah); cudaGetSymbolAddress((void**)&wqal, g_wqal);
    cudaGetSymbolAddress((void**)&wqbh, g_wqbh); cudaGetSymbolAddress((void**)&wqbl, g_wqbl);
    cudaGetSymbolAddress((void**)&wkvh, g_wkvh); cudaGetSymbolAddress((void**)&wkvl, g_wkvl);
    cudaGetSymbolAddress((void**)&wkbh, g_wkbh); cudaGetSymbolAddress((void**)&wkbl, g_wkbl);
    cudaGetSymbolAddress((void**)&wvbh, g_wvbh); cudaGetSymbolAddress((void**)&wvbl, g_wvbl);

    // one-time stream/event creation (first call is outside graph capture)
    static cudaStream_t s1 = nullptr, s2 = nullptr;
    static cudaEvent_t evX = nullptr, evKV = nullptr, ev1 = nullptr, ev2 = nullptr;
    if (!s1) {
        cudaStreamCreateWithFlags(&s1, cudaStreamNonBlocking);
        cudaStreamCreateWithFlags(&s2, cudaStreamNonBlocking);
        cudaEventCreateWithFlags(&evX, cudaEventDisableTiming);
        cudaEventCreateWithFlags(&evKV, cudaEventDisableTiming);
        cudaEventCreateWithFlags(&ev1, cudaEventDisableTiming);
        cudaEventCreateWithFlags(&ev2, cudaEventDisableTiming);
        cudaFuncSetAttribute(gemm_mma, cudaFuncAttributeMaxDynamicSharedMemorySize,
                             GEMM_SMEM_BYTES);
        cudaFuncSetAttribute(gemm_f16, cudaFuncAttributeMaxDynamicSharedMemorySize,
                             GEMMH_SMEM_BYTES);
        cudaFuncSetAttribute(flash_mma, cudaFuncAttributeMaxDynamicSharedMemorySize,
                             FLASH_SMEM_BYTES);
    }
    cudaStream_t s0 = 0;   // legacy default stream (capture origin)

    // ---- s0: shared input conversion, then fork ----
    conv_on(s0, x, xh, xl, TOKENS * DMODEL);
    cudaEventRecord(evX, s0);

    // ---- s1: q chain ----
    cudaStreamWaitEvent(s1, evX, 0);
    conv_on(s1, q_a_w, wqah, wqal, QLATD * DMODEL);
    conv_on(s1, q_b_w, wqbh, wqbl, DMODEL * QLATD);
    gemm_mma<<<dim3(QLATD / 128, TOKENS / 128), 128, GEMM_SMEM_BYTES, s1>>>(
        xh, xl, wqah, wqal, nullptr, qlh, qll, nullptr, TOKENS, QLATD, DMODEL);
    gemm_mma<<<dim3(DMODEL / 128, TOKENS / 128), 128, GEMM_SMEM_BYTES, s1>>>(
        qlh, qll, wqbh, wqbl, q, nullptr, nullptr, nullptr, TOKENS, DMODEL, QLATD);
    norm_rope_kernel<<<TOKENS * NHEADS, 128, 0, s1>>>(q, q_nw, qh, ql);
    cudaEventRecord(ev1, s1);

    // ---- s0: kv chain ----
    conv_on(s0, kv_a_w, wkvh, wkvl, KVLATD * DMODEL);
    conv_on(s0, k_b_w, wkbh, wkbl, DMODEL * KVLATD);
    conv_on(s0, v_b_w, wvbh, wvbl, DMODEL * KVLATD);
    conv_f16<<<(DMODEL * DMODEL / 4 + 255) / 256, 256, 0, s0>>>(
        o_w, owf, DMODEL * DMODEL / 4);
    gemm_mma<<<dim3(KVLATD / 128, TOKENS / 128), 128, GEMM_SMEM_BYTES, s0>>>(
        xh, xl, wkvh, wkvl, nullptr, kvh, kvl, nullptr, TOKENS, KVLATD, DMODEL);
    cudaEventRecord(evKV, s0);
    // s2: v_b in parallel with k_b
    cudaStreamWaitEvent(s2, evKV, 0);
    gemm_mma<<<dim3(DMODEL / 128, TOKENS / 128), 128, GEMM_SMEM_BYTES, s2>>>(
        kvh, kvl, wvbh, wvbl, nullptr, nullptr, nullptr, vf, TOKENS, DMODEL, KVLATD);
    cudaEventRecord(ev2, s2);
    // s0: k_b + norm
    gemm_mma<<<dim3(DMODEL / 128, TOKENS / 128), 128, GEMM_SMEM_BYTES, s0>>>(
        kvh, kvl, wkbh, wkbl, k, nullptr, nullptr, nullptr, TOKENS, DMODEL, KVLATD);
    norm_rope_kernel<<<TOKENS * NHEADS, 128, 0, s0>>>(k, k_nw, kh, kl);

    // ---- join: flash needs q chain (ev1) and v_b (ev2); k chain is on s0 ----
    cudaStreamWaitEvent(s0, ev1, 0);
    cudaStreamWaitEvent(s0, ev2, 0);
    flash_mma<<<dim3(TSEQ / 128, 2 * NHEADS), 256, FLASH_SMEM_BYTES, s0>>>(
        qh, ql, kh, kl, vf, aof);

    // output projection: single-product fp16 -> fp32 d_out
    gemm_f16<<<dim3(DMODEL / 128, TOKENS / 128), 128, GEMMH_SMEM_BYTES, s0>>>(
        aof, owf, (float*)d_out, TOKENS, DMODEL, DMODEL);
}